// round 4
// baseline (speedup 1.0000x reference)
#include <cuda_runtime.h>
#include <cuda_bf16.h>
#include <math.h>

// Problem dims (fixed)
#define Bb 64
#define Tt 512
#define IN_DIM 512
#define Hh 1024
#define G4 4096
#define NCLS 1000
#define NBLK 128   // persistent grid size; <= 148 SMs -> single wave guaranteed

// Scratch (device globals; no allocation allowed)
__device__ float g_xg[(size_t)Bb * Tt * G4];     // 512 MB: pre-activation gates (reused by both layers)
__device__ float g_hs[(size_t)Bb * Tt * Hh];     // 128 MB: layer-0 outputs
__device__ float g_hT0[Hh * Bb];                 // h transposed [H][B], ping
__device__ float g_hT1[Hh * Bb];                 // pong
__device__ float g_hlast[Bb * Hh];               // layer-1 h (row-major), feeds FC

// Grid-barrier state (monotonic epoch survives graph replays; logic is relative)
__device__ unsigned g_bar_count = 0;
__device__ unsigned g_bar_epoch = 0;

// ---------------------------------------------------------------------------
// zero2: zero the recurrent h buffers
// ---------------------------------------------------------------------------
__global__ void zero2_kernel(float* a, float* b, int n) {
    int i = blockIdx.x * blockDim.x + threadIdx.x;
    if (i < n) { a[i] = 0.f; b[i] = 0.f; }
}

// ---------------------------------------------------------------------------
// sgemm_bias: C[M,N] = A[M,K] @ W[N,K]^T + bias1[N] (+ bias2[N])
// 128x64 tile, BK=16, 256 threads, 8x4 per thread.
// ---------------------------------------------------------------------------
__global__ void sgemm_bias_kernel(const float* __restrict__ A,
                                  const float* __restrict__ W,
                                  const float* __restrict__ bias1,
                                  const float* __restrict__ bias2,
                                  float* __restrict__ C,
                                  int M, int N, int K) {
    __shared__ __align__(16) float As[16 * 132];
    __shared__ __align__(16) float Ws[16 * 68];
    const int m0 = blockIdx.y * 128;
    const int n0 = blockIdx.x * 64;
    const int tid = threadIdx.x;
    const int tx = tid & 15;   // n quad (4 cols)
    const int ty = tid >> 4;   // m octet (8 rows)
    float acc[8][4] = {};

    for (int k0 = 0; k0 < K; k0 += 16) {
#pragma unroll
        for (int i = 0; i < 8; i++) {
            int idx = tid + i * 256;        // 0..2047
            int k = idx & 15;
            int r = idx >> 4;               // 0..127
            As[k * 132 + r] = (m0 + r < M) ? A[(long)(m0 + r) * K + k0 + k] : 0.f;
        }
#pragma unroll
        for (int i = 0; i < 4; i++) {
            int idx = tid + i * 256;        // 0..1023
            int k = idx & 15;
            int r = idx >> 4;               // 0..63
            Ws[k * 68 + r] = (n0 + r < N) ? W[(long)(n0 + r) * K + k0 + k] : 0.f;
        }
        __syncthreads();
#pragma unroll
        for (int kk = 0; kk < 16; kk++) {
            float4 b = *(const float4*)&Ws[kk * 68 + tx * 4];
            float4 a0 = *(const float4*)&As[kk * 132 + ty * 8];
            float4 a1 = *(const float4*)&As[kk * 132 + ty * 8 + 4];
            acc[0][0] += a0.x * b.x; acc[0][1] += a0.x * b.y; acc[0][2] += a0.x * b.z; acc[0][3] += a0.x * b.w;
            acc[1][0] += a0.y * b.x; acc[1][1] += a0.y * b.y; acc[1][2] += a0.y * b.z; acc[1][3] += a0.y * b.w;
            acc[2][0] += a0.z * b.x; acc[2][1] += a0.z * b.y; acc[2][2] += a0.z * b.z; acc[2][3] += a0.z * b.w;
            acc[3][0] += a0.w * b.x; acc[3][1] += a0.w * b.y; acc[3][2] += a0.w * b.z; acc[3][3] += a0.w * b.w;
            acc[4][0] += a1.x * b.x; acc[4][1] += a1.x * b.y; acc[4][2] += a1.x * b.z; acc[4][3] += a1.x * b.w;
            acc[5][0] += a1.y * b.x; acc[5][1] += a1.y * b.y; acc[5][2] += a1.y * b.z; acc[5][3] += a1.y * b.w;
            acc[6][0] += a1.z * b.x; acc[6][1] += a1.z * b.y; acc[6][2] += a1.z * b.z; acc[6][3] += a1.z * b.w;
            acc[7][0] += a1.w * b.x; acc[7][1] += a1.w * b.y; acc[7][2] += a1.w * b.z; acc[7][3] += a1.w * b.w;
        }
        __syncthreads();
    }

#pragma unroll
    for (int i = 0; i < 8; i++) {
        int m = m0 + ty * 8 + i;
        if (m >= M) continue;
#pragma unroll
        for (int j = 0; j < 4; j++) {
            int n = n0 + tx * 4 + j;
            if (n >= N) continue;
            float bsum = (bias1 ? bias1[n] : 0.f) + (bias2 ? bias2[n] : 0.f);
            C[(long)m * N + n] = acc[i][j] + bsum;
        }
    }
}

// ---------------------------------------------------------------------------
// Persistent LSTM layer: all 512 timesteps in ONE kernel.
// 128 blocks (single wave), block owns 8 j-rows x all 4 gates x all 64 batch.
// W_hh slice cached in dynamic smem once. c state lives in registers.
// Cross-block h handoff via software grid barrier (volatile epoch + fences).
// ---------------------------------------------------------------------------
__device__ __forceinline__ void grid_barrier(unsigned target) {
    __threadfence();            // publish this thread's writes (all threads)
    __syncthreads();
    if (threadIdx.x == 0) {
        unsigned arrived = atomicAdd(&g_bar_count, 1u);
        if (arrived == NBLK - 1) {
            *(volatile unsigned*)&g_bar_count = 0u;
            __threadfence();
            *(volatile unsigned*)&g_bar_epoch = target;
        } else {
            while (*(volatile unsigned*)&g_bar_epoch < target) { }
        }
    }
    __syncthreads();
}

// dynamic smem layout (floats):
//   Wsm : 32*1024  = 32768   W_hh slice, [k][jj*4+gate]
//   Hs  : 16*64    = 1024    h tile [k][b]
//   Xs  : 32*64    = 2048    xg step tile [gate*8+jj][b]
//   Os  : 8*64     = 512     h output stage [jj][b]
#define SM_W  0
#define SM_H  (32 * Hh)
#define SM_X  (SM_H + 16 * 64)
#define SM_O  (SM_X + 32 * 64)
#define SM_TOT (SM_O + 8 * 64)

__global__ __launch_bounds__(256, 1)
void lstm_persist_kernel(const float* __restrict__ xg,
                         const float* __restrict__ W_hh,
                         float* h0, float* h1,
                         float* __restrict__ hs_out,   // [b][t][j] (layer0) or row-major h (layer1)
                         int store_seq) {               // 1: store full sequence; 0: only last h
    extern __shared__ float smem[];
    float* Wsm = smem + SM_W;
    float* Hs  = smem + SM_H;
    float* Xs  = smem + SM_X;
    float* Os  = smem + SM_O;

    const int tid = threadIdx.x;       // 256
    const int bp = tid & 31;           // b pair
    const int jl = tid >> 5;           // 0..7
    const int j0 = blockIdx.x * 8;
    const int jg = j0 + jl;

    __shared__ unsigned s_e0;
    if (tid == 0) s_e0 = *(volatile unsigned*)&g_bar_epoch;
    __syncthreads();
    const unsigned e0 = s_e0;

    // Preload this block's W_hh slice (32 rows x 1024 k) into smem, swizzled.
    for (int idx = tid; idx < 32 * Hh; idx += 256) {
        int k = idx & (Hh - 1);
        int r = idx >> 10;               // 0..31
        int gate = r >> 3;
        int jj = r & 7;
        Wsm[k * 32 + jj * 4 + gate] = W_hh[(long)(gate * Hh + j0 + jj) * Hh + k];
    }

    float cst[2] = {0.f, 0.f};
    const float* hin = h0;
    float* hout = h1;
    __syncthreads();

    for (int t = 0; t < Tt; t++) {
        float acc[4][2] = {};
        const volatile float* hv = hin;   // L1-bypass: must see other blocks' writes

        // Stage xg tile for this step: coalesced (8 contiguous floats per (b,gate)).
        // Xs written here, first read after the k0 loop (many syncs in between).
#pragma unroll
        for (int i = 0; i < 8; i++) {
            int idx = tid + i * 256;       // 0..2047
            int jj = idx & 7;
            int gate = (idx >> 3) & 3;
            int b = idx >> 5;
            Xs[(gate * 8 + jj) * 64 + b] =
                xg[((long)b * Tt + t) * G4 + gate * Hh + j0 + jj];
        }

        for (int k0 = 0; k0 < Hh; k0 += 16) {
#pragma unroll
            for (int i = 0; i < 4; i++) {
                int idx = tid + i * 256;
                int b = idx & 63;
                int k = idx >> 6;
                Hs[k * 64 + b] = hv[(k0 + k) * 64 + b];
            }
            __syncthreads();
#pragma unroll
            for (int kk = 0; kk < 16; kk++) {
                float4 w = *(const float4*)&Wsm[(k0 + kk) * 32 + jl * 4]; // i,f,g,o
                float2 h = *(const float2*)&Hs[kk * 64 + bp * 2];
                acc[0][0] += w.x * h.x; acc[0][1] += w.x * h.y;
                acc[1][0] += w.y * h.x; acc[1][1] += w.y * h.y;
                acc[2][0] += w.z * h.x; acc[2][1] += w.z * h.y;
                acc[3][0] += w.w * h.x; acc[3][1] += w.w * h.y;
            }
            __syncthreads();
        }

        // Pointwise LSTM; gate pre-activations from smem (coalesced-staged).
#pragma unroll
        for (int bl = 0; bl < 2; bl++) {
            int b = bp * 2 + bl;
            float pi = acc[0][bl] + Xs[(0 * 8 + jl) * 64 + b];
            float pf = acc[1][bl] + Xs[(1 * 8 + jl) * 64 + b];
            float pg = acc[2][bl] + Xs[(2 * 8 + jl) * 64 + b];
            float po = acc[3][bl] + Xs[(3 * 8 + jl) * 64 + b];
            float gi = 1.f / (1.f + expf(-pi));
            float gf = 1.f / (1.f + expf(-pf));
            float gg = tanhf(pg);
            float go = 1.f / (1.f + expf(-po));
            float c = gf * cst[bl] + gi * gg;
            cst[bl] = c;
            float h = go * tanhf(c);
            hout[jg * 64 + b] = h;         // coalesced: b contiguous per (jl) warp
            Os[jl * 64 + b] = h;           // stage for coalesced seq store
        }

        if (store_seq) {
            __syncthreads();   // Os complete
            // hs_out[b][t][j0+jj]: 8 contiguous floats per b -> coalesced chunks
#pragma unroll
            for (int i = 0; i < 2; i++) {
                int idx = tid + i * 256;   // 0..511
                int jj = idx & 7;
                int b = idx >> 3;
                hs_out[((long)b * Tt + t) * Hh + j0 + jj] = Os[jj * 64 + b];
            }
        } else if (t == Tt - 1) {
            __syncthreads();
#pragma unroll
            for (int i = 0; i < 2; i++) {
                int idx = tid + i * 256;
                int jj = idx & 7;
                int b = idx >> 3;
                hs_out[(long)b * Hh + j0 + jj] = Os[jj * 64 + b];
            }
        }

        grid_barrier(e0 + (unsigned)t + 1u);

        const float* tmp = hin; hin = hout; hout = (float*)tmp;
    }
}

// ---------------------------------------------------------------------------
// kernel_launch: 7 graph nodes total
// ---------------------------------------------------------------------------
extern "C" void kernel_launch(void* const* d_in, const int* in_sizes, int n_in,
                              void* d_out, int out_size) {
    const float* x     = (const float*)d_in[0];
    const float* W_ih0 = (const float*)d_in[1];
    const float* W_hh0 = (const float*)d_in[2];
    const float* b_ih0 = (const float*)d_in[3];
    const float* b_hh0 = (const float*)d_in[4];
    const float* W_ih1 = (const float*)d_in[5];
    const float* W_hh1 = (const float*)d_in[6];
    const float* b_ih1 = (const float*)d_in[7];
    const float* b_hh1 = (const float*)d_in[8];
    const float* fc_w  = (const float*)d_in[9];
    const float* fc_b  = (const float*)d_in[10];
    float* out = (float*)d_out;

    float *xg, *hs, *hT0, *hT1, *hlast;
    cudaGetSymbolAddress((void**)&xg, g_xg);
    cudaGetSymbolAddress((void**)&hs, g_hs);
    cudaGetSymbolAddress((void**)&hT0, g_hT0);
    cudaGetSymbolAddress((void**)&hT1, g_hT1);
    cudaGetSymbolAddress((void**)&hlast, g_hlast);

    const int stateN = Hh * Bb;  // 65536
    const int SMEM_PERSIST = SM_TOT * sizeof(float);  // 145,  ~141.5 KB

    static int smem_set = 0;
    if (!smem_set) {
        cudaFuncSetAttribute(lstm_persist_kernel,
                             cudaFuncAttributeMaxDynamicSharedMemorySize,
                             SMEM_PERSIST);
        smem_set = 1;
    }

    // ---------------- Layer 0 ----------------
    zero2_kernel<<<(stateN + 255) / 256, 256>>>(hT0, hT1, stateN);

    {   // xg0 = x @ W_ih0^T + b_ih0 + b_hh0   (M=32768, N=4096, K=512)
        dim3 grid(G4 / 64, (Bb * Tt) / 128);
        sgemm_bias_kernel<<<grid, 256>>>(x, W_ih0, b_ih0, b_hh0, xg,
                                         Bb * Tt, G4, IN_DIM);
    }

    lstm_persist_kernel<<<NBLK, 256, SMEM_PERSIST>>>(
        xg, W_hh0, hT0, hT1, hs, 1);

    // ---------------- Layer 1 ----------------
    zero2_kernel<<<(stateN + 255) / 256, 256>>>(hT0, hT1, stateN);

    {   // xg1 = hs0 @ W_ih1^T + b_ih1 + b_hh1   (M=32768, N=4096, K=1024)
        dim3 grid(G4 / 64, (Bb * Tt) / 128);
        sgemm_bias_kernel<<<grid, 256>>>(hs, W_ih1, b_ih1, b_hh1, xg,
                                         Bb * Tt, G4, Hh);
    }

    lstm_persist_kernel<<<NBLK, 256, SMEM_PERSIST>>>(
        xg, W_hh1, hT0, hT1, hlast, 0);

    // ---------------- FC ----------------
    {   // out[64,1000] = hlast @ fc_w^T + fc_b
        dim3 grid((NCLS + 63) / 64, (Bb + 127) / 128);
        sgemm_bias_kernel<<<grid, 256>>>(hlast, fc_w, fc_b, nullptr, out,
                                         Bb, NCLS, Hh);
    }
}

// round 5
// speedup vs baseline: 1.1474x; 1.1474x over previous
#include <cuda_runtime.h>
#include <cuda_bf16.h>
#include <math.h>
#include <stdint.h>

// Problem dims (fixed)
#define Bb 64
#define Tt 512
#define IN_DIM 512
#define Hh 1024
#define G4 4096
#define NCLS 1000
#define NBLK 128   // persistent grid size; <= 148 SMs -> single wave guaranteed

// Scratch (device globals; no allocation allowed)
__device__ float g_xg[(size_t)Bb * Tt * G4];     // 512 MB: pre-activation gates (reused by both layers)
__device__ float g_hs[(size_t)Bb * Tt * Hh];     // 128 MB: layer-0 outputs
__device__ float g_hT0[Hh * Bb];                 // h transposed [H][B], ping
__device__ float g_hT1[Hh * Bb];                 // pong
__device__ float g_hlast[Bb * Hh];               // layer-1 h (row-major), feeds FC

// Grid-barrier state (monotonic epoch survives graph replays; logic is relative)
__device__ unsigned g_bar_count = 0;
__device__ unsigned g_bar_epoch = 0;

// ---------------------------------------------------------------------------
// zero2
// ---------------------------------------------------------------------------
__global__ void zero2_kernel(float* a, float* b, int n) {
    int i = blockIdx.x * blockDim.x + threadIdx.x;
    if (i < n) { a[i] = 0.f; b[i] = 0.f; }
}

// ---------------------------------------------------------------------------
// tf32 helpers
// ---------------------------------------------------------------------------
__device__ __forceinline__ float f2tf32(float x) {
    uint32_t u;
    asm("cvt.rna.tf32.f32 %0, %1;" : "=r"(u) : "f"(x));
    return __uint_as_float(u);
}

__device__ __forceinline__ void mma_tf32(float c[4],
                                         uint32_t a0, uint32_t a1, uint32_t a2, uint32_t a3,
                                         uint32_t b0, uint32_t b1) {
    asm volatile(
        "mma.sync.aligned.m16n8k8.row.col.f32.tf32.tf32.f32 "
        "{%0,%1,%2,%3}, {%4,%5,%6,%7}, {%8,%9}, {%0,%1,%2,%3};"
        : "+f"(c[0]), "+f"(c[1]), "+f"(c[2]), "+f"(c[3])
        : "r"(a0), "r"(a1), "r"(a2), "r"(a3), "r"(b0), "r"(b1));
}

// ---------------------------------------------------------------------------
// tf32 tensor-core GEMM: C[M,N] = A[M,K] @ W[N,K]^T + bias1[N] + bias2[N]
// REQUIRES: M%128==0, N%128==0, K%32==0 (used only for the layer GEMMs).
// Block 128x128, 256 threads (8 warps, 2x4), warp tile 64x32 (4x4 m16n8k8).
// ---------------------------------------------------------------------------
__global__ __launch_bounds__(256, 2)
void tf32_gemm_bias_kernel(const float* __restrict__ A,
                           const float* __restrict__ W,
                           const float* __restrict__ bias1,
                           const float* __restrict__ bias2,
                           float* __restrict__ C,
                           int M, int N, int K) {
    __shared__ __align__(16) float As[128 * 36];
    __shared__ __align__(16) float Ws[128 * 36];

    const int tid  = threadIdx.x;
    const int lane = tid & 31;
    const int warp = tid >> 5;
    const int wm = warp >> 2;           // 0..1 -> m offset wm*64
    const int wn = warp & 3;            // 0..3 -> n offset wn*32
    const int g  = lane >> 2;           // groupID 0..7
    const int tg = lane & 3;            // threadInGroup 0..3

    const long m0 = (long)blockIdx.y * 128;
    const long n0 = (long)blockIdx.x * 128;

    float acc[4][4][4];                 // [m-tile][n-tile][4 regs]
#pragma unroll
    for (int i = 0; i < 4; i++)
#pragma unroll
        for (int j = 0; j < 4; j++)
#pragma unroll
            for (int r = 0; r < 4; r++) acc[i][j][r] = 0.f;

    for (int k0 = 0; k0 < K; k0 += 32) {
        // Stage A,W tiles (128x32) -> smem, rounding to tf32.
#pragma unroll
        for (int i = 0; i < 4; i++) {
            int idx = tid + i * 256;            // 0..1023
            int r = idx >> 3;                   // 0..127
            int c4 = (idx & 7) * 4;             // 0,4,..28
            float4 va = *(const float4*)&A[(m0 + r) * K + k0 + c4];
            float4 vw = *(const float4*)&W[(n0 + r) * K + k0 + c4];
            va.x = f2tf32(va.x); va.y = f2tf32(va.y); va.z = f2tf32(va.z); va.w = f2tf32(va.w);
            vw.x = f2tf32(vw.x); vw.y = f2tf32(vw.y); vw.z = f2tf32(vw.z); vw.w = f2tf32(vw.w);
            *(float4*)&As[r * 36 + c4] = va;
            *(float4*)&Ws[r * 36 + c4] = vw;
        }
        __syncthreads();

#pragma unroll
        for (int k8 = 0; k8 < 4; k8++) {
            const int kb = k8 * 8;
            // A fragments: 4 m-tiles
            uint32_t af[4][4];
#pragma unroll
            for (int mt = 0; mt < 4; mt++) {
                const float* ab = &As[(wm * 64 + mt * 16 + g) * 36 + kb + tg];
                af[mt][0] = __float_as_uint(ab[0]);
                af[mt][2] = __float_as_uint(ab[4]);
                af[mt][1] = __float_as_uint(ab[8 * 36]);
                af[mt][3] = __float_as_uint(ab[8 * 36 + 4]);
            }
            // B fragments: 4 n-tiles
            uint32_t bf[4][2];
#pragma unroll
            for (int nt = 0; nt < 4; nt++) {
                const float* bb = &Ws[(wn * 32 + nt * 8 + g) * 36 + kb + tg];
                bf[nt][0] = __float_as_uint(bb[0]);
                bf[nt][1] = __float_as_uint(bb[4]);
            }
#pragma unroll
            for (int mt = 0; mt < 4; mt++)
#pragma unroll
                for (int nt = 0; nt < 4; nt++)
                    mma_tf32(acc[mt][nt], af[mt][0], af[mt][1], af[mt][2], af[mt][3],
                             bf[nt][0], bf[nt][1]);
        }
        __syncthreads();
    }

    // Epilogue: bias + store (float2 per c-pair)
#pragma unroll
    for (int mt = 0; mt < 4; mt++) {
#pragma unroll
        for (int nt = 0; nt < 4; nt++) {
            long row0 = m0 + wm * 64 + mt * 16 + g;
            long col  = n0 + wn * 32 + nt * 8 + tg * 2;
            float bsum0 = (bias1 ? bias1[col]     : 0.f) + (bias2 ? bias2[col]     : 0.f);
            float bsum1 = (bias1 ? bias1[col + 1] : 0.f) + (bias2 ? bias2[col + 1] : 0.f);
            float2 v0 = make_float2(acc[mt][nt][0] + bsum0, acc[mt][nt][1] + bsum1);
            float2 v1 = make_float2(acc[mt][nt][2] + bsum0, acc[mt][nt][3] + bsum1);
            *(float2*)&C[row0 * N + col] = v0;
            *(float2*)&C[(row0 + 8) * N + col] = v1;
        }
    }
}

// ---------------------------------------------------------------------------
// fp32 SGEMM (kept for the small FC with bounds checks)
// ---------------------------------------------------------------------------
__global__ void sgemm_bias_kernel(const float* __restrict__ A,
                                  const float* __restrict__ W,
                                  const float* __restrict__ bias1,
                                  const float* __restrict__ bias2,
                                  float* __restrict__ C,
                                  int M, int N, int K) {
    __shared__ __align__(16) float As[16 * 132];
    __shared__ __align__(16) float Ws[16 * 68];
    const int m0 = blockIdx.y * 128;
    const int n0 = blockIdx.x * 64;
    const int tid = threadIdx.x;
    const int tx = tid & 15;
    const int ty = tid >> 4;
    float acc[8][4] = {};

    for (int k0 = 0; k0 < K; k0 += 16) {
#pragma unroll
        for (int i = 0; i < 8; i++) {
            int idx = tid + i * 256;
            int k = idx & 15;
            int r = idx >> 4;
            As[k * 132 + r] = (m0 + r < M) ? A[(long)(m0 + r) * K + k0 + k] : 0.f;
        }
#pragma unroll
        for (int i = 0; i < 4; i++) {
            int idx = tid + i * 256;
            int k = idx & 15;
            int r = idx >> 4;
            Ws[k * 68 + r] = (n0 + r < N) ? W[(long)(n0 + r) * K + k0 + k] : 0.f;
        }
        __syncthreads();
#pragma unroll
        for (int kk = 0; kk < 16; kk++) {
            float4 b = *(const float4*)&Ws[kk * 68 + tx * 4];
            float4 a0 = *(const float4*)&As[kk * 132 + ty * 8];
            float4 a1 = *(const float4*)&As[kk * 132 + ty * 8 + 4];
            acc[0][0] += a0.x * b.x; acc[0][1] += a0.x * b.y; acc[0][2] += a0.x * b.z; acc[0][3] += a0.x * b.w;
            acc[1][0] += a0.y * b.x; acc[1][1] += a0.y * b.y; acc[1][2] += a0.y * b.z; acc[1][3] += a0.y * b.w;
            acc[2][0] += a0.z * b.x; acc[2][1] += a0.z * b.y; acc[2][2] += a0.z * b.z; acc[2][3] += a0.z * b.w;
            acc[3][0] += a0.w * b.x; acc[3][1] += a0.w * b.y; acc[3][2] += a0.w * b.z; acc[3][3] += a0.w * b.w;
            acc[4][0] += a1.x * b.x; acc[4][1] += a1.x * b.y; acc[4][2] += a1.x * b.z; acc[4][3] += a1.x * b.w;
            acc[5][0] += a1.y * b.x; acc[5][1] += a1.y * b.y; acc[5][2] += a1.y * b.z; acc[5][3] += a1.y * b.w;
            acc[6][0] += a1.z * b.x; acc[6][1] += a1.z * b.y; acc[6][2] += a1.z * b.z; acc[6][3] += a1.z * b.w;
            acc[7][0] += a1.w * b.x; acc[7][1] += a1.w * b.y; acc[7][2] += a1.w * b.z; acc[7][3] += a1.w * b.w;
        }
        __syncthreads();
    }

#pragma unroll
    for (int i = 0; i < 8; i++) {
        int m = m0 + ty * 8 + i;
        if (m >= M) continue;
#pragma unroll
        for (int j = 0; j < 4; j++) {
            int n = n0 + tx * 4 + j;
            if (n >= N) continue;
            float bsum = (bias1 ? bias1[n] : 0.f) + (bias2 ? bias2[n] : 0.f);
            C[(long)m * N + n] = acc[i][j] + bsum;
        }
    }
}

// ---------------------------------------------------------------------------
// Persistent LSTM layer (unchanged from passing R4 version)
// ---------------------------------------------------------------------------
__device__ __forceinline__ void grid_barrier(unsigned target) {
    __threadfence();
    __syncthreads();
    if (threadIdx.x == 0) {
        unsigned arrived = atomicAdd(&g_bar_count, 1u);
        if (arrived == NBLK - 1) {
            *(volatile unsigned*)&g_bar_count = 0u;
            __threadfence();
            *(volatile unsigned*)&g_bar_epoch = target;
        } else {
            while (*(volatile unsigned*)&g_bar_epoch < target) { }
        }
    }
    __syncthreads();
}

#define SM_W  0
#define SM_H  (32 * Hh)
#define SM_X  (SM_H + 16 * 64)
#define SM_O  (SM_X + 32 * 64)
#define SM_TOT (SM_O + 8 * 64)

__global__ __launch_bounds__(256, 1)
void lstm_persist_kernel(const float* __restrict__ xg,
                         const float* __restrict__ W_hh,
                         float* h0, float* h1,
                         float* __restrict__ hs_out,
                         int store_seq) {
    extern __shared__ float smem[];
    float* Wsm = smem + SM_W;
    float* Hs  = smem + SM_H;
    float* Xs  = smem + SM_X;
    float* Os  = smem + SM_O;

    const int tid = threadIdx.x;
    const int bp = tid & 31;
    const int jl = tid >> 5;
    const int j0 = blockIdx.x * 8;
    const int jg = j0 + jl;

    __shared__ unsigned s_e0;
    if (tid == 0) s_e0 = *(volatile unsigned*)&g_bar_epoch;
    __syncthreads();
    const unsigned e0 = s_e0;

    for (int idx = tid; idx < 32 * Hh; idx += 256) {
        int k = idx & (Hh - 1);
        int r = idx >> 10;
        int gate = r >> 3;
        int jj = r & 7;
        Wsm[k * 32 + jj * 4 + gate] = W_hh[(long)(gate * Hh + j0 + jj) * Hh + k];
    }

    float cst[2] = {0.f, 0.f};
    const float* hin = h0;
    float* hout = h1;
    __syncthreads();

    for (int t = 0; t < Tt; t++) {
        float acc[4][2] = {};
        const volatile float* hv = hin;

#pragma unroll
        for (int i = 0; i < 8; i++) {
            int idx = tid + i * 256;
            int jj = idx & 7;
            int gate = (idx >> 3) & 3;
            int b = idx >> 5;
            Xs[(gate * 8 + jj) * 64 + b] =
                xg[((long)b * Tt + t) * G4 + gate * Hh + j0 + jj];
        }

        for (int k0 = 0; k0 < Hh; k0 += 16) {
#pragma unroll
            for (int i = 0; i < 4; i++) {
                int idx = tid + i * 256;
                int b = idx & 63;
                int k = idx >> 6;
                Hs[k * 64 + b] = hv[(k0 + k) * 64 + b];
            }
            __syncthreads();
#pragma unroll
            for (int kk = 0; kk < 16; kk++) {
                float4 w = *(const float4*)&Wsm[(k0 + kk) * 32 + jl * 4];
                float2 h = *(const float2*)&Hs[kk * 64 + bp * 2];
                acc[0][0] += w.x * h.x; acc[0][1] += w.x * h.y;
                acc[1][0] += w.y * h.x; acc[1][1] += w.y * h.y;
                acc[2][0] += w.z * h.x; acc[2][1] += w.z * h.y;
                acc[3][0] += w.w * h.x; acc[3][1] += w.w * h.y;
            }
            __syncthreads();
        }

#pragma unroll
        for (int bl = 0; bl < 2; bl++) {
            int b = bp * 2 + bl;
            float pi = acc[0][bl] + Xs[(0 * 8 + jl) * 64 + b];
            float pf = acc[1][bl] + Xs[(1 * 8 + jl) * 64 + b];
            float pg = acc[2][bl] + Xs[(2 * 8 + jl) * 64 + b];
            float po = acc[3][bl] + Xs[(3 * 8 + jl) * 64 + b];
            float gi = 1.f / (1.f + expf(-pi));
            float gf = 1.f / (1.f + expf(-pf));
            float gg = tanhf(pg);
            float go = 1.f / (1.f + expf(-po));
            float c = gf * cst[bl] + gi * gg;
            cst[bl] = c;
            float h = go * tanhf(c);
            hout[jg * 64 + b] = h;
            Os[jl * 64 + b] = h;
        }

        if (store_seq) {
            __syncthreads();
#pragma unroll
            for (int i = 0; i < 2; i++) {
                int idx = tid + i * 256;
                int jj = idx & 7;
                int b = idx >> 3;
                hs_out[((long)b * Tt + t) * Hh + j0 + jj] = Os[jj * 64 + b];
            }
        } else if (t == Tt - 1) {
            __syncthreads();
#pragma unroll
            for (int i = 0; i < 2; i++) {
                int idx = tid + i * 256;
                int jj = idx & 7;
                int b = idx >> 3;
                hs_out[(long)b * Hh + j0 + jj] = Os[jj * 64 + b];
            }
        }

        grid_barrier(e0 + (unsigned)t + 1u);

        const float* tmp = hin; hin = hout; hout = (float*)tmp;
    }
}

// ---------------------------------------------------------------------------
// kernel_launch: 7 graph nodes total
// ---------------------------------------------------------------------------
extern "C" void kernel_launch(void* const* d_in, const int* in_sizes, int n_in,
                              void* d_out, int out_size) {
    const float* x     = (const float*)d_in[0];
    const float* W_ih0 = (const float*)d_in[1];
    const float* W_hh0 = (const float*)d_in[2];
    const float* b_ih0 = (const float*)d_in[3];
    const float* b_hh0 = (const float*)d_in[4];
    const float* W_ih1 = (const float*)d_in[5];
    const float* W_hh1 = (const float*)d_in[6];
    const float* b_ih1 = (const float*)d_in[7];
    const float* b_hh1 = (const float*)d_in[8];
    const float* fc_w  = (const float*)d_in[9];
    const float* fc_b  = (const float*)d_in[10];
    float* out = (float*)d_out;

    float *xg, *hs, *hT0, *hT1, *hlast;
    cudaGetSymbolAddress((void**)&xg, g_xg);
    cudaGetSymbolAddress((void**)&hs, g_hs);
    cudaGetSymbolAddress((void**)&hT0, g_hT0);
    cudaGetSymbolAddress((void**)&hT1, g_hT1);
    cudaGetSymbolAddress((void**)&hlast, g_hlast);

    const int stateN = Hh * Bb;  // 65536
    const int SMEM_PERSIST = SM_TOT * sizeof(float);

    static int smem_set = 0;
    if (!smem_set) {
        cudaFuncSetAttribute(lstm_persist_kernel,
                             cudaFuncAttributeMaxDynamicSharedMemorySize,
                             SMEM_PERSIST);
        smem_set = 1;
    }

    // ---------------- Layer 0 ----------------
    zero2_kernel<<<(stateN + 255) / 256, 256>>>(hT0, hT1, stateN);

    {   // xg0 = x @ W_ih0^T + b_ih0 + b_hh0   (M=32768, N=4096, K=512)
        dim3 grid(G4 / 128, (Bb * Tt) / 128);
        tf32_gemm_bias_kernel<<<grid, 256>>>(x, W_ih0, b_ih0, b_hh0, xg,
                                             Bb * Tt, G4, IN_DIM);
    }

    lstm_persist_kernel<<<NBLK, 256, SMEM_PERSIST>>>(
        xg, W_hh0, hT0, hT1, hs, 1);

    // ---------------- Layer 1 ----------------
    zero2_kernel<<<(stateN + 255) / 256, 256>>>(hT0, hT1, stateN);

    {   // xg1 = hs0 @ W_ih1^T + b_ih1 + b_hh1   (M=32768, N=4096, K=1024)
        dim3 grid(G4 / 128, (Bb * Tt) / 128);
        tf32_gemm_bias_kernel<<<grid, 256>>>(hs, W_ih1, b_ih1, b_hh1, xg,
                                             Bb * Tt, G4, Hh);
    }

    lstm_persist_kernel<<<NBLK, 256, SMEM_PERSIST>>>(
        xg, W_hh1, hT0, hT1, hlast, 0);

    // ---------------- FC ----------------
    {   // out[64,1000] = hlast @ fc_w^T + fc_b
        dim3 grid((NCLS + 63) / 64, (Bb + 127) / 128);
        sgemm_bias_kernel<<<grid, 256>>>(hlast, fc_w, fc_b, nullptr, out,
                                         Bb, NCLS, Hh);
    }
}

// round 7
// speedup vs baseline: 2.8793x; 2.5094x over previous
#include <cuda_runtime.h>
#include <cuda_bf16.h>
#include <math.h>
#include <stdint.h>

// Problem dims (fixed)
#define Bb 64
#define Tt 512
#define IN_DIM 512
#define Hh 1024
#define G4 4096
#define NCLS 1000
#define NBLK 128   // persistent grid size; <= 148 SMs -> single wave guaranteed

// Scratch (device globals; no allocation allowed)
__device__ float g_xg[(size_t)Bb * Tt * G4];
__device__ float g_hs[(size_t)Bb * Tt * Hh];
__device__ float g_hT0[Hh * Bb];
__device__ float g_hT1[Hh * Bb];
__device__ float g_hlast[Bb * Hh];

__device__ unsigned g_bar_count = 0;
__device__ unsigned g_bar_epoch = 0;

// ---------------------------------------------------------------------------
__global__ void zero2_kernel(float* a, float* b, int n) {
    int i = blockIdx.x * blockDim.x + threadIdx.x;
    if (i < n) { a[i] = 0.f; b[i] = 0.f; }
}

// ---------------------------------------------------------------------------
// tf32 helpers
// ---------------------------------------------------------------------------
__device__ __forceinline__ float f2tf32(float x) {
    uint32_t u;
    asm("cvt.rna.tf32.f32 %0, %1;" : "=r"(u) : "f"(x));
    return __uint_as_float(u);
}

__device__ __forceinline__ void mma_tf32(float c[4],
                                         uint32_t a0, uint32_t a1, uint32_t a2, uint32_t a3,
                                         uint32_t b0, uint32_t b1) {
    asm volatile(
        "mma.sync.aligned.m16n8k8.row.col.f32.tf32.tf32.f32 "
        "{%0,%1,%2,%3}, {%4,%5,%6,%7}, {%8,%9}, {%0,%1,%2,%3};"
        : "+f"(c[0]), "+f"(c[1]), "+f"(c[2]), "+f"(c[3])
        : "r"(a0), "r"(a1), "r"(a2), "r"(a3), "r"(b0), "r"(b1));
}

// ---------------------------------------------------------------------------
// tf32 tensor-core GEMM (proven): C = A @ W^T + bias1 + bias2
// REQUIRES: M%128==0, N%128==0, K%32==0.
// ---------------------------------------------------------------------------
__global__ __launch_bounds__(256, 2)
void tf32_gemm_bias_kernel(const float* __restrict__ A,
                           const float* __restrict__ W,
                           const float* __restrict__ bias1,
                           const float* __restrict__ bias2,
                           float* __restrict__ C,
                           int M, int N, int K) {
    __shared__ __align__(16) float As[128 * 36];
    __shared__ __align__(16) float Ws[128 * 36];

    const int tid  = threadIdx.x;
    const int lane = tid & 31;
    const int warp = tid >> 5;
    const int wm = warp >> 2;
    const int wn = warp & 3;
    const int g  = lane >> 2;
    const int tg = lane & 3;

    const long m0 = (long)blockIdx.y * 128;
    const long n0 = (long)blockIdx.x * 128;

    float acc[4][4][4];
#pragma unroll
    for (int i = 0; i < 4; i++)
#pragma unroll
        for (int j = 0; j < 4; j++)
#pragma unroll
            for (int r = 0; r < 4; r++) acc[i][j][r] = 0.f;

    for (int k0 = 0; k0 < K; k0 += 32) {
#pragma unroll
        for (int i = 0; i < 4; i++) {
            int idx = tid + i * 256;
            int r = idx >> 3;
            int c4 = (idx & 7) * 4;
            float4 va = *(const float4*)&A[(m0 + r) * K + k0 + c4];
            float4 vw = *(const float4*)&W[(n0 + r) * K + k0 + c4];
            va.x = f2tf32(va.x); va.y = f2tf32(va.y); va.z = f2tf32(va.z); va.w = f2tf32(va.w);
            vw.x = f2tf32(vw.x); vw.y = f2tf32(vw.y); vw.z = f2tf32(vw.z); vw.w = f2tf32(vw.w);
            *(float4*)&As[r * 36 + c4] = va;
            *(float4*)&Ws[r * 36 + c4] = vw;
        }
        __syncthreads();

#pragma unroll
        for (int k8 = 0; k8 < 4; k8++) {
            const int kb = k8 * 8;
            uint32_t af[4][4];
#pragma unroll
            for (int mt = 0; mt < 4; mt++) {
                const float* ab = &As[(wm * 64 + mt * 16 + g) * 36 + kb + tg];
                af[mt][0] = __float_as_uint(ab[0]);
                af[mt][2] = __float_as_uint(ab[4]);
                af[mt][1] = __float_as_uint(ab[8 * 36]);
                af[mt][3] = __float_as_uint(ab[8 * 36 + 4]);
            }
            uint32_t bf[4][2];
#pragma unroll
            for (int nt = 0; nt < 4; nt++) {
                const float* bb = &Ws[(wn * 32 + nt * 8 + g) * 36 + kb + tg];
                bf[nt][0] = __float_as_uint(bb[0]);
                bf[nt][1] = __float_as_uint(bb[4]);
            }
#pragma unroll
            for (int mt = 0; mt < 4; mt++)
#pragma unroll
                for (int nt = 0; nt < 4; nt++)
                    mma_tf32(acc[mt][nt], af[mt][0], af[mt][1], af[mt][2], af[mt][3],
                             bf[nt][0], bf[nt][1]);
        }
        __syncthreads();
    }

#pragma unroll
    for (int mt = 0; mt < 4; mt++) {
#pragma unroll
        for (int nt = 0; nt < 4; nt++) {
            long row0 = m0 + wm * 64 + mt * 16 + g;
            long col  = n0 + wn * 32 + nt * 8 + tg * 2;
            float bsum0 = (bias1 ? bias1[col]     : 0.f) + (bias2 ? bias2[col]     : 0.f);
            float bsum1 = (bias1 ? bias1[col + 1] : 0.f) + (bias2 ? bias2[col + 1] : 0.f);
            float2 v0 = make_float2(acc[mt][nt][0] + bsum0, acc[mt][nt][1] + bsum1);
            float2 v1 = make_float2(acc[mt][nt][2] + bsum0, acc[mt][nt][3] + bsum1);
            *(float2*)&C[row0 * N + col] = v0;
            *(float2*)&C[(row0 + 8) * N + col] = v1;
        }
    }
}

// ---------------------------------------------------------------------------
// fp32 SGEMM (FC only)
// ---------------------------------------------------------------------------
__global__ void sgemm_bias_kernel(const float* __restrict__ A,
                                  const float* __restrict__ W,
                                  const float* __restrict__ bias1,
                                  const float* __restrict__ bias2,
                                  float* __restrict__ C,
                                  int M, int N, int K) {
    __shared__ __align__(16) float As[16 * 132];
    __shared__ __align__(16) float Ws[16 * 68];
    const int m0 = blockIdx.y * 128;
    const int n0 = blockIdx.x * 64;
    const int tid = threadIdx.x;
    const int tx = tid & 15;
    const int ty = tid >> 4;
    float acc[8][4] = {};

    for (int k0 = 0; k0 < K; k0 += 16) {
#pragma unroll
        for (int i = 0; i < 8; i++) {
            int idx = tid + i * 256;
            int k = idx & 15;
            int r = idx >> 4;
            As[k * 132 + r] = (m0 + r < M) ? A[(long)(m0 + r) * K + k0 + k] : 0.f;
        }
#pragma unroll
        for (int i = 0; i < 4; i++) {
            int idx = tid + i * 256;
            int k = idx & 15;
            int r = idx >> 4;
            Ws[k * 68 + r] = (n0 + r < N) ? W[(long)(n0 + r) * K + k0 + k] : 0.f;
        }
        __syncthreads();
#pragma unroll
        for (int kk = 0; kk < 16; kk++) {
            float4 b = *(const float4*)&Ws[kk * 68 + tx * 4];
            float4 a0 = *(const float4*)&As[kk * 132 + ty * 8];
            float4 a1 = *(const float4*)&As[kk * 132 + ty * 8 + 4];
            acc[0][0] += a0.x * b.x; acc[0][1] += a0.x * b.y; acc[0][2] += a0.x * b.z; acc[0][3] += a0.x * b.w;
            acc[1][0] += a0.y * b.x; acc[1][1] += a0.y * b.y; acc[1][2] += a0.y * b.z; acc[1][3] += a0.y * b.w;
            acc[2][0] += a0.z * b.x; acc[2][1] += a0.z * b.y; acc[2][2] += a0.z * b.z; acc[2][3] += a0.z * b.w;
            acc[3][0] += a0.w * b.x; acc[3][1] += a0.w * b.y; acc[3][2] += a0.w * b.z; acc[3][3] += a0.w * b.w;
            acc[4][0] += a1.x * b.x; acc[4][1] += a1.x * b.y; acc[4][2] += a1.x * b.z; acc[4][3] += a1.x * b.w;
            acc[5][0] += a1.y * b.x; acc[5][1] += a1.y * b.y; acc[5][2] += a1.y * b.z; acc[5][3] += a1.y * b.w;
            acc[6][0] += a1.z * b.x; acc[6][1] += a1.z * b.y; acc[6][2] += a1.z * b.z; acc[6][3] += a1.z * b.w;
            acc[7][0] += a1.w * b.x; acc[7][1] += a1.w * b.y; acc[7][2] += a1.w * b.z; acc[7][3] += a1.w * b.w;
        }
        __syncthreads();
    }

#pragma unroll
    for (int i = 0; i < 8; i++) {
        int m = m0 + ty * 8 + i;
        if (m >= M) continue;
#pragma unroll
        for (int j = 0; j < 4; j++) {
            int n = n0 + tx * 4 + j;
            if (n >= N) continue;
            float bsum = (bias1 ? bias1[n] : 0.f) + (bias2 ? bias2[n] : 0.f);
            C[(long)m * N + n] = acc[i][j] + bsum;
        }
    }
}

// ---------------------------------------------------------------------------
__device__ __forceinline__ void grid_barrier(unsigned target) {
    __threadfence();
    __syncthreads();
    if (threadIdx.x == 0) {
        unsigned arrived = atomicAdd(&g_bar_count, 1u);
        if (arrived == NBLK - 1) {
            *(volatile unsigned*)&g_bar_count = 0u;
            __threadfence();
            *(volatile unsigned*)&g_bar_epoch = target;
        } else {
            while (*(volatile unsigned*)&g_bar_epoch < target) { }
        }
    }
    __syncthreads();
}

// ---------------------------------------------------------------------------
// Persistent LSTM layer with tf32 tensor-core recurrence.
// 128 blocks, block owns 32 gate-rows (4 gates x 8 j) x 64 batch x 1024 k.
// W pre-fragmented in smem (128KB, tf32). h staged per 128-k chunk into
// fragment-order smem (double buffered). mma m16n8k8 tf32, fp32 accumulators.
// ---------------------------------------------------------------------------
#define SMF_WF 0
#define SMF_HF 32768
#define SMF_DS (SMF_HF + 16896)
#define SMF_XS (SMF_DS + 2112)
#define SMF_OS (SMF_XS + 2048)
#define SMF_TOT (SMF_OS + 512)          // 54336 floats = 217344 bytes
#define HFBUF 4224                      // float2 per buffer (16 k8 * 8 nt * 33)

__global__ __launch_bounds__(256, 1)
void lstm_persist_mma_kernel(const float* __restrict__ xg,
                             const float* __restrict__ W_hh,
                             float* h0, float* h1,
                             float* __restrict__ hs_out,
                             int store_seq) {
    extern __shared__ float smem[];
    float4* Wf4 = (float4*)(smem + SMF_WF);
    float2* Hf2 = (float2*)(smem + SMF_HF);
    float*  Ds  = smem + SMF_DS;
    float*  Xs  = smem + SMF_XS;
    float*  Os  = smem + SMF_OS;

    const int tid  = threadIdx.x;      // 256
    const int lane = tid & 31;
    const int warp = tid >> 5;         // 0..7
    const int g  = lane >> 2;
    const int tg = lane & 3;
    const int mt = warp & 1;           // m-tile (rows mt*16..mt*16+15)
    const int np = warp >> 1;          // n-pair 0..3
    const int nt0 = np * 2, nt1 = np * 2 + 1;

    const int j0 = blockIdx.x * 8;
    const int bp = tid & 31;           // pointwise: batch pair
    const int jl = tid >> 5;           // pointwise: j within block
    const int jg = j0 + jl;

    __shared__ unsigned s_e0;
    if (tid == 0) s_e0 = *(volatile unsigned*)&g_bar_epoch;
    __syncthreads();
    const unsigned e0 = s_e0;

    // ---- one-time: W_hh -> A-fragment smem (tf32-rounded) ----
    for (int f4i = tid; f4i < 8192; f4i += 256) {
        int l   = f4i & 31;
        int grp = f4i >> 5;            // 0..255
        int k8  = grp & 127;
        int mtl = grp >> 7;
        int gg = l >> 2, tt = l & 3;
        int r0 = mtl * 16 + gg;
        int r1 = r0 + 8;
        int k  = k8 * 8 + tt;
        long row0 = (long)((r0 >> 3) * Hh + j0 + (r0 & 7)) * Hh;
        long row1 = (long)((r1 >> 3) * Hh + j0 + (r1 & 7)) * Hh;
        float4 v;
        v.x = f2tf32(W_hh[row0 + k]);
        v.y = f2tf32(W_hh[row1 + k]);
        v.z = f2tf32(W_hh[row0 + k + 4]);
        v.w = f2tf32(W_hh[row1 + k + 4]);
        Wf4[f4i] = v;
    }

    float cst[2] = {0.f, 0.f};
    const float* hin = h0;
    float* hout = h1;
    __syncthreads();

    for (int t = 0; t < Tt; t++) {
        float acc0[4] = {0.f, 0.f, 0.f, 0.f};
        float acc1[4] = {0.f, 0.f, 0.f, 0.f};

        // Stage xg tile (read after Ds sync; coalesced 32B chunks)
#pragma unroll
        for (int i = 0; i < 8; i++) {
            int idx = tid + i * 256;
            int jj = idx & 7;
            int gate = (idx >> 3) & 3;
            int b = idx >> 5;
            Xs[(gate * 8 + jj) * 64 + b] =
                xg[((long)b * Tt + t) * G4 + gate * Hh + j0 + jj];
        }

        // ---- stage chunk 0 of h into Hf buf 0 ----
        {
            const int c = 0;
#pragma unroll
            for (int i = 0; i < 4; i++) {
                int tau = tid + i * 256;        // 0..1023
                int kp = tau >> 4;              // 0..63
                int bq = tau & 15;
                int k8l = kp >> 2;              // 0..15
                int tt = kp & 3;
                int k = c * 128 + k8l * 8 + tt;
                float4 va = __ldcg((const float4*)(hin + (long)k * 64 + bq * 4));
                float4 vb = __ldcg((const float4*)(hin + (long)(k + 4) * 64 + bq * 4));
                float av[4] = {va.x, va.y, va.z, va.w};
                float bv[4] = {vb.x, vb.y, vb.z, vb.w};
#pragma unroll
                for (int ii = 0; ii < 4; ii++) {
                    int b = bq * 4 + ii;
                    int nt = b >> 3, gg = b & 7;
                    Hf2[(k8l * 8 + nt) * 33 + gg * 4 + tt] =
                        make_float2(f2tf32(av[ii]), f2tf32(bv[ii]));
                }
            }
        }
        __syncthreads();

        // ---- 8 chunks of 128 k: stage(c+1) overlapped with mma(c) ----
        for (int c = 0; c < 8; c++) {
            if (c < 7) {
                const int cn = c + 1;
                float2* Hw = Hf2 + (cn & 1) * HFBUF;
#pragma unroll
                for (int i = 0; i < 4; i++) {
                    int tau = tid + i * 256;
                    int kp = tau >> 4;
                    int bq = tau & 15;
                    int k8l = kp >> 2;
                    int tt = kp & 3;
                    int k = cn * 128 + k8l * 8 + tt;
                    float4 va = __ldcg((const float4*)(hin + (long)k * 64 + bq * 4));
                    float4 vb = __ldcg((const float4*)(hin + (long)(k + 4) * 64 + bq * 4));
                    float av[4] = {va.x, va.y, va.z, va.w};
                    float bv[4] = {vb.x, vb.y, vb.z, vb.w};
#pragma unroll
                    for (int ii = 0; ii < 4; ii++) {
                        int b = bq * 4 + ii;
                        int nt = b >> 3, gg = b & 7;
                        Hw[(k8l * 8 + nt) * 33 + gg * 4 + tt] =
                            make_float2(f2tf32(av[ii]), f2tf32(bv[ii]));
                    }
                }
            }

            const float2* Hr = Hf2 + (c & 1) * HFBUF;
            const float4* Wb = Wf4 + (mt * 128 + c * 16) * 32 + lane;
#pragma unroll 8
            for (int k8l = 0; k8l < 16; k8l++) {
                float4 A  = Wb[k8l * 32];
                float2 B0 = Hr[(k8l * 8 + nt0) * 33 + lane];
                float2 B1 = Hr[(k8l * 8 + nt1) * 33 + lane];
                uint32_t a0 = __float_as_uint(A.x), a1 = __float_as_uint(A.y);
                uint32_t a2 = __float_as_uint(A.z), a3 = __float_as_uint(A.w);
                mma_tf32(acc0, a0, a1, a2, a3,
                         __float_as_uint(B0.x), __float_as_uint(B0.y));
                mma_tf32(acc1, a0, a1, a2, a3,
                         __float_as_uint(B1.x), __float_as_uint(B1.y));
            }
            __syncthreads();
        }

        // ---- scatter D to smem in [row][b] layout ----
        {
            int r0 = mt * 16 + g;
            Ds[r0 * 66 + nt0 * 8 + tg * 2]     = acc0[0];
            Ds[r0 * 66 + nt0 * 8 + tg * 2 + 1] = acc0[1];
            Ds[(r0 + 8) * 66 + nt0 * 8 + tg * 2]     = acc0[2];
            Ds[(r0 + 8) * 66 + nt0 * 8 + tg * 2 + 1] = acc0[3];
            Ds[r0 * 66 + nt1 * 8 + tg * 2]     = acc1[0];
            Ds[r0 * 66 + nt1 * 8 + tg * 2 + 1] = acc1[1];
            Ds[(r0 + 8) * 66 + nt1 * 8 + tg * 2]     = acc1[2];
            Ds[(r0 + 8) * 66 + nt1 * 8 + tg * 2 + 1] = acc1[3];
        }
        __syncthreads();

        // ---- pointwise LSTM ----
#pragma unroll
        for (int bl = 0; bl < 2; bl++) {
            int b = bp * 2 + bl;
            float pi = Ds[(0  + jl) * 66 + b] + Xs[(0  + jl) * 64 + b];
            float pf = Ds[(8  + jl) * 66 + b] + Xs[(8  + jl) * 64 + b];
            float pg = Ds[(16 + jl) * 66 + b] + Xs[(16 + jl) * 64 + b];
            float po = Ds[(24 + jl) * 66 + b] + Xs[(24 + jl) * 64 + b];
            float gi = 1.f / (1.f + expf(-pi));
            float gf = 1.f / (1.f + expf(-pf));
            float gg = tanhf(pg);
            float go = 1.f / (1.f + expf(-po));
            float c = gf * cst[bl] + gi * gg;
            cst[bl] = c;
            float h = go * tanhf(c);
            hout[jg * 64 + b] = h;
            Os[jl * 64 + b] = h;
        }

        if (store_seq) {
            __syncthreads();
#pragma unroll
            for (int i = 0; i < 2; i++) {
                int idx = tid + i * 256;
                int jj = idx & 7;
                int b = idx >> 3;
                hs_out[((long)b * Tt + t) * Hh + j0 + jj] = Os[jj * 64 + b];
            }
        } else if (t == Tt - 1) {
            __syncthreads();
#pragma unroll
            for (int i = 0; i < 2; i++) {
                int idx = tid + i * 256;
                int jj = idx & 7;
                int b = idx >> 3;
                hs_out[(long)b * Hh + j0 + jj] = Os[jj * 64 + b];
            }
        }

        grid_barrier(e0 + (unsigned)t + 1u);

        const float* tmp = hin; hin = hout; hout = (float*)tmp;
    }
}

// ---------------------------------------------------------------------------
// kernel_launch: 7 graph nodes total
// ---------------------------------------------------------------------------
extern "C" void kernel_launch(void* const* d_in, const int* in_sizes, int n_in,
                              void* d_out, int out_size) {
    const float* x     = (const float*)d_in[0];
    const float* W_ih0 = (const float*)d_in[1];
    const float* W_hh0 = (const float*)d_in[2];
    const float* b_ih0 = (const float*)d_in[3];
    const float* b_hh0 = (const float*)d_in[4];
    const float* W_ih1 = (const float*)d_in[5];
    const float* W_hh1 = (const float*)d_in[6];
    const float* b_ih1 = (const float*)d_in[7];
    const float* b_hh1 = (const float*)d_in[8];
    const float* fc_w  = (const float*)d_in[9];
    const float* fc_b  = (const float*)d_in[10];
    float* out = (float*)d_out;

    float *xg, *hs, *hT0, *hT1, *hlast;
    cudaGetSymbolAddress((void**)&xg, g_xg);
    cudaGetSymbolAddress((void**)&hs, g_hs);
    cudaGetSymbolAddress((void**)&hT0, g_hT0);
    cudaGetSymbolAddress((void**)&hT1, g_hT1);
    cudaGetSymbolAddress((void**)&hlast, g_hlast);

    const int stateN = Hh * Bb;
    const int SMEM_PERSIST = SMF_TOT * sizeof(float);   // 217344 B

    static int smem_set = 0;
    if (!smem_set) {
        cudaFuncSetAttribute(lstm_persist_mma_kernel,
                             cudaFuncAttributeMaxDynamicSharedMemorySize,
                             SMEM_PERSIST);
        smem_set = 1;
    }

    // ---------------- Layer 0 ----------------
    zero2_kernel<<<(stateN + 255) / 256, 256>>>(hT0, hT1, stateN);

    {   // xg0 = x @ W_ih0^T + b_ih0 + b_hh0
        dim3 grid(G4 / 128, (Bb * Tt) / 128);
        tf32_gemm_bias_kernel<<<grid, 256>>>(x, W_ih0, b_ih0, b_hh0, xg,
                                             Bb * Tt, G4, IN_DIM);
    }

    lstm_persist_mma_kernel<<<NBLK, 256, SMEM_PERSIST>>>(
        xg, W_hh0, hT0, hT1, hs, 1);

    // ---------------- Layer 1 ----------------
    zero2_kernel<<<(stateN + 255) / 256, 256>>>(hT0, hT1, stateN);

    {   // xg1 = hs0 @ W_ih1^T + b_ih1 + b_hh1
        dim3 grid(G4 / 128, (Bb * Tt) / 128);
        tf32_gemm_bias_kernel<<<grid, 256>>>(hs, W_ih1, b_ih1, b_hh1, xg,
                                             Bb * Tt, G4, Hh);
    }

    lstm_persist_mma_kernel<<<NBLK, 256, SMEM_PERSIST>>>(
        xg, W_hh1, hT0, hT1, hlast, 0);

    // ---------------- FC ----------------
    {
        dim3 grid((NCLS + 63) / 64, (Bb + 127) / 128);
        sgemm_bias_kernel<<<grid, 256>>>(hlast, fc_w, fc_b, nullptr, out,
                                         Bb, NCLS, Hh);
    }
}

// round 8
// speedup vs baseline: 3.8325x; 1.3310x over previous
#include <cuda_runtime.h>
#include <cuda_bf16.h>
#include <math.h>
#include <stdint.h>

// Problem dims (fixed)
#define Bb 64
#define Tt 512
#define IN_DIM 512
#define Hh 1024
#define G4 4096
#define NCLS 1000
#define NBLK 128   // persistent grid; single wave on 148 SMs

// Scratch (device globals; no allocation allowed)
__device__ float  g_xg[(size_t)Bb * Tt * G4];
__device__ float  g_hs[(size_t)Bb * Tt * Hh];
__device__ float2 g_hfA[Hh * Bb / 2];   // h in B-fragment layout, ping
__device__ float2 g_hfB[Hh * Bb / 2];   // pong
__device__ float  g_hlast[Bb * Hh];

__device__ unsigned g_bar_count = 0;
__device__ unsigned g_bar_epoch = 0;

// ---------------------------------------------------------------------------
__global__ void zero2_kernel(float* a, float* b, int n) {
    int i = blockIdx.x * blockDim.x + threadIdx.x;
    if (i < n) { a[i] = 0.f; b[i] = 0.f; }
}

// ---------------------------------------------------------------------------
// tf32 helpers
// ---------------------------------------------------------------------------
__device__ __forceinline__ float f2tf32(float x) {
    uint32_t u;
    asm("cvt.rna.tf32.f32 %0, %1;" : "=r"(u) : "f"(x));
    return __uint_as_float(u);
}

__device__ __forceinline__ void mma_tf32(float c[4],
                                         uint32_t a0, uint32_t a1, uint32_t a2, uint32_t a3,
                                         uint32_t b0, uint32_t b1) {
    asm volatile(
        "mma.sync.aligned.m16n8k8.row.col.f32.tf32.tf32.f32 "
        "{%0,%1,%2,%3}, {%4,%5,%6,%7}, {%8,%9}, {%0,%1,%2,%3};"
        : "+f"(c[0]), "+f"(c[1]), "+f"(c[2]), "+f"(c[3])
        : "r"(a0), "r"(a1), "r"(a2), "r"(a3), "r"(b0), "r"(b1));
}

// ---------------------------------------------------------------------------
// tf32 tensor-core GEMM (proven): C = A @ W^T + bias1 + bias2
// REQUIRES: M%128==0, N%128==0, K%32==0.
// ---------------------------------------------------------------------------
__global__ __launch_bounds__(256, 2)
void tf32_gemm_bias_kernel(const float* __restrict__ A,
                           const float* __restrict__ W,
                           const float* __restrict__ bias1,
                           const float* __restrict__ bias2,
                           float* __restrict__ C,
                           int M, int N, int K) {
    __shared__ __align__(16) float As[128 * 36];
    __shared__ __align__(16) float Ws[128 * 36];

    const int tid  = threadIdx.x;
    const int lane = tid & 31;
    const int warp = tid >> 5;
    const int wm = warp >> 2;
    const int wn = warp & 3;
    const int g  = lane >> 2;
    const int tg = lane & 3;

    const long m0 = (long)blockIdx.y * 128;
    const long n0 = (long)blockIdx.x * 128;

    float acc[4][4][4];
#pragma unroll
    for (int i = 0; i < 4; i++)
#pragma unroll
        for (int j = 0; j < 4; j++)
#pragma unroll
            for (int r = 0; r < 4; r++) acc[i][j][r] = 0.f;

    for (int k0 = 0; k0 < K; k0 += 32) {
#pragma unroll
        for (int i = 0; i < 4; i++) {
            int idx = tid + i * 256;
            int r = idx >> 3;
            int c4 = (idx & 7) * 4;
            float4 va = *(const float4*)&A[(m0 + r) * K + k0 + c4];
            float4 vw = *(const float4*)&W[(n0 + r) * K + k0 + c4];
            va.x = f2tf32(va.x); va.y = f2tf32(va.y); va.z = f2tf32(va.z); va.w = f2tf32(va.w);
            vw.x = f2tf32(vw.x); vw.y = f2tf32(vw.y); vw.z = f2tf32(vw.z); vw.w = f2tf32(vw.w);
            *(float4*)&As[r * 36 + c4] = va;
            *(float4*)&Ws[r * 36 + c4] = vw;
        }
        __syncthreads();

#pragma unroll
        for (int k8 = 0; k8 < 4; k8++) {
            const int kb = k8 * 8;
            uint32_t af[4][4];
#pragma unroll
            for (int mt = 0; mt < 4; mt++) {
                const float* ab = &As[(wm * 64 + mt * 16 + g) * 36 + kb + tg];
                af[mt][0] = __float_as_uint(ab[0]);
                af[mt][2] = __float_as_uint(ab[4]);
                af[mt][1] = __float_as_uint(ab[8 * 36]);
                af[mt][3] = __float_as_uint(ab[8 * 36 + 4]);
            }
            uint32_t bf[4][2];
#pragma unroll
            for (int nt = 0; nt < 4; nt++) {
                const float* bb = &Ws[(wn * 32 + nt * 8 + g) * 36 + kb + tg];
                bf[nt][0] = __float_as_uint(bb[0]);
                bf[nt][1] = __float_as_uint(bb[4]);
            }
#pragma unroll
            for (int mt = 0; mt < 4; mt++)
#pragma unroll
                for (int nt = 0; nt < 4; nt++)
                    mma_tf32(acc[mt][nt], af[mt][0], af[mt][1], af[mt][2], af[mt][3],
                             bf[nt][0], bf[nt][1]);
        }
        __syncthreads();
    }

#pragma unroll
    for (int mt = 0; mt < 4; mt++) {
#pragma unroll
        for (int nt = 0; nt < 4; nt++) {
            long row0 = m0 + wm * 64 + mt * 16 + g;
            long col  = n0 + wn * 32 + nt * 8 + tg * 2;
            float bsum0 = (bias1 ? bias1[col]     : 0.f) + (bias2 ? bias2[col]     : 0.f);
            float bsum1 = (bias1 ? bias1[col + 1] : 0.f) + (bias2 ? bias2[col + 1] : 0.f);
            float2 v0 = make_float2(acc[mt][nt][0] + bsum0, acc[mt][nt][1] + bsum1);
            float2 v1 = make_float2(acc[mt][nt][2] + bsum0, acc[mt][nt][3] + bsum1);
            *(float2*)&C[row0 * N + col] = v0;
            *(float2*)&C[(row0 + 8) * N + col] = v1;
        }
    }
}

// ---------------------------------------------------------------------------
// fp32 SGEMM (FC only)
// ---------------------------------------------------------------------------
__global__ void sgemm_bias_kernel(const float* __restrict__ A,
                                  const float* __restrict__ W,
                                  const float* __restrict__ bias1,
                                  const float* __restrict__ bias2,
                                  float* __restrict__ C,
                                  int M, int N, int K) {
    __shared__ __align__(16) float As[16 * 132];
    __shared__ __align__(16) float Ws[16 * 68];
    const int m0 = blockIdx.y * 128;
    const int n0 = blockIdx.x * 64;
    const int tid = threadIdx.x;
    const int tx = tid & 15;
    const int ty = tid >> 4;
    float acc[8][4] = {};

    for (int k0 = 0; k0 < K; k0 += 16) {
#pragma unroll
        for (int i = 0; i < 8; i++) {
            int idx = tid + i * 256;
            int k = idx & 15;
            int r = idx >> 4;
            As[k * 132 + r] = (m0 + r < M) ? A[(long)(m0 + r) * K + k0 + k] : 0.f;
        }
#pragma unroll
        for (int i = 0; i < 4; i++) {
            int idx = tid + i * 256;
            int k = idx & 15;
            int r = idx >> 4;
            Ws[k * 68 + r] = (n0 + r < N) ? W[(long)(n0 + r) * K + k0 + k] : 0.f;
        }
        __syncthreads();
#pragma unroll
        for (int kk = 0; kk < 16; kk++) {
            float4 b = *(const float4*)&Ws[kk * 68 + tx * 4];
            float4 a0 = *(const float4*)&As[kk * 132 + ty * 8];
            float4 a1 = *(const float4*)&As[kk * 132 + ty * 8 + 4];
            acc[0][0] += a0.x * b.x; acc[0][1] += a0.x * b.y; acc[0][2] += a0.x * b.z; acc[0][3] += a0.x * b.w;
            acc[1][0] += a0.y * b.x; acc[1][1] += a0.y * b.y; acc[1][2] += a0.y * b.z; acc[1][3] += a0.y * b.w;
            acc[2][0] += a0.z * b.x; acc[2][1] += a0.z * b.y; acc[2][2] += a0.z * b.z; acc[2][3] += a0.z * b.w;
            acc[3][0] += a0.w * b.x; acc[3][1] += a0.w * b.y; acc[3][2] += a0.w * b.z; acc[3][3] += a0.w * b.w;
            acc[4][0] += a1.x * b.x; acc[4][1] += a1.x * b.y; acc[4][2] += a1.x * b.z; acc[4][3] += a1.x * b.w;
            acc[5][0] += a1.y * b.x; acc[5][1] += a1.y * b.y; acc[5][2] += a1.y * b.z; acc[5][3] += a1.y * b.w;
            acc[6][0] += a1.z * b.x; acc[6][1] += a1.z * b.y; acc[6][2] += a1.z * b.z; acc[6][3] += a1.z * b.w;
            acc[7][0] += a1.w * b.x; acc[7][1] += a1.w * b.y; acc[7][2] += a1.w * b.z; acc[7][3] += a1.w * b.w;
        }
        __syncthreads();
    }

#pragma unroll
    for (int i = 0; i < 8; i++) {
        int m = m0 + ty * 8 + i;
        if (m >= M) continue;
#pragma unroll
        for (int j = 0; j < 4; j++) {
            int n = n0 + tx * 4 + j;
            if (n >= N) continue;
            float bsum = (bias1 ? bias1[n] : 0.f) + (bias2 ? bias2[n] : 0.f);
            C[(long)m * N + n] = acc[i][j] + bsum;
        }
    }
}

// ---------------------------------------------------------------------------
// Persistent LSTM, tf32 mma, h exchanged in B-fragment layout in GLOBAL.
//
// hfrag layout (float2): hf[(k8*8 + nt)*32 + gg*4 + tg]
//   .x = h[j = 8*k8 + tg    ][b = nt*8 + gg]   (tf32-rounded)
//   .y = h[j = 8*k8 + 4 + tg][b = nt*8 + gg]
// Producer block bid owns k8 = bid (j = 8*bid..8*bid+7).
// Consumer warp w (nt = w) loads one float2 per k8: a perfectly coalesced
// 256B line, L2-broadcast to all blocks. No smem staging of h at all.
//
// smem (floats): Wf4 32768 | Ds 2112 | Xs 2048 | Os 512  -> 149,760 B
// ---------------------------------------------------------------------------
#define SMP_W  0
#define SMP_DS 32768
#define SMP_XS (SMP_DS + 2112)
#define SMP_OS (SMP_XS + 2048)
#define SMP_TOT (SMP_OS + 512)

__global__ __launch_bounds__(256, 1)
void lstm_persist_mma2_kernel(const float* __restrict__ xg,
                              const float* __restrict__ W_hh,
                              float2* hfA, float2* hfB,
                              float* __restrict__ hs_out,
                              int store_seq) {
    extern __shared__ float smem[];
    float4* Wf4 = (float4*)(smem + SMP_W);
    float*  Ds  = smem + SMP_DS;
    float*  Xs  = smem + SMP_XS;
    float*  Os  = smem + SMP_OS;

    const int tid  = threadIdx.x;      // 256
    const int lane = tid & 31;
    const int w    = tid >> 5;         // warp 0..7 == nt == jl
    const int g    = lane >> 2;
    const int tg   = lane & 3;
    const int bid  = blockIdx.x;
    const int j0   = bid * 8;
    const int bp   = lane;             // pointwise batch-pair
    const int jl   = w;

    __shared__ unsigned s_e0;
    if (tid == 0) s_e0 = *(volatile unsigned*)&g_bar_epoch;
    __syncthreads();
    const unsigned e0 = s_e0;

    // ---- one-time: W_hh -> A-fragment smem (tf32), proven layout ----
    for (int f4i = tid; f4i < 8192; f4i += 256) {
        int l   = f4i & 31;
        int grp = f4i >> 5;            // 0..255
        int k8  = grp & 127;
        int mtl = grp >> 7;
        int gg = l >> 2, tt = l & 3;
        int r0 = mtl * 16 + gg;
        int r1 = r0 + 8;
        int k  = k8 * 8 + tt;
        long row0 = (long)((r0 >> 3) * Hh + j0 + (r0 & 7)) * Hh;
        long row1 = (long)((r1 >> 3) * Hh + j0 + (r1 & 7)) * Hh;
        float4 v;
        v.x = f2tf32(W_hh[row0 + k]);
        v.y = f2tf32(W_hh[row1 + k]);
        v.z = f2tf32(W_hh[row0 + k + 4]);
        v.w = f2tf32(W_hh[row1 + k + 4]);
        Wf4[f4i] = v;
    }

    float cst[2] = {0.f, 0.f};
    const float2* hfin = hfA;
    float2* hfout = hfB;
    __syncthreads();

    // stage Xs for t=0
#pragma unroll
    for (int i = 0; i < 8; i++) {
        int idx = tid + i * 256;
        int jj = idx & 7;
        int gate = (idx >> 3) & 3;
        int b = idx >> 5;
        Xs[(gate * 8 + jj) * 64 + b] =
            xg[((long)b * Tt + 0) * G4 + gate * Hh + j0 + jj];
    }

    for (int t = 0; t < Tt; t++) {
        float acc0[4] = {0.f, 0.f, 0.f, 0.f};   // mt=0: rows 0..15
        float acc1[4] = {0.f, 0.f, 0.f, 0.f};   // mt=1: rows 16..31

        // ---- mma loop: B from global frag buffer, A from smem ----
        const float2* hbase = hfin + w * 32 + lane;   // + k8*256
        float2 Bq[8];
#pragma unroll
        for (int p = 0; p < 8; p++) Bq[p] = __ldcg(hbase + p * 256);
        float4 A0n = Wf4[lane];
        float4 A1n = Wf4[128 * 32 + lane];

#pragma unroll 8
        for (int k8 = 0; k8 < 128; k8++) {
            float4 A0 = A0n, A1 = A1n;
            float2 B  = Bq[k8 & 7];
            if (k8 < 127) {
                A0n = Wf4[(k8 + 1) * 32 + lane];
                A1n = Wf4[(128 + k8 + 1) * 32 + lane];
            }
            if (k8 + 8 < 128) Bq[k8 & 7] = __ldcg(hbase + (k8 + 8) * 256);
            uint32_t b0 = __float_as_uint(B.x), b1 = __float_as_uint(B.y);
            mma_tf32(acc0, __float_as_uint(A0.x), __float_as_uint(A0.y),
                            __float_as_uint(A0.z), __float_as_uint(A0.w), b0, b1);
            mma_tf32(acc1, __float_as_uint(A1.x), __float_as_uint(A1.y),
                            __float_as_uint(A1.z), __float_as_uint(A1.w), b0, b1);
        }

        // ---- D scatter: warp w owns cols w*8+tg*2 (+1), rows via g ----
        {
            int c0 = w * 8 + tg * 2;
            Ds[g * 66 + c0]            = acc0[0];
            Ds[g * 66 + c0 + 1]        = acc0[1];
            Ds[(g + 8) * 66 + c0]      = acc0[2];
            Ds[(g + 8) * 66 + c0 + 1]  = acc0[3];
            Ds[(16 + g) * 66 + c0]     = acc1[0];
            Ds[(16 + g) * 66 + c0 + 1] = acc1[1];
            Ds[(24 + g) * 66 + c0]     = acc1[2];
            Ds[(24 + g) * 66 + c0 + 1] = acc1[3];
        }
        __syncthreads();

        // ---- pointwise LSTM; write h straight to frag buffer ----
#pragma unroll
        for (int bl = 0; bl < 2; bl++) {
            int b = bp * 2 + bl;
            float pi = Ds[jl * 66 + b]        + Xs[jl * 64 + b];
            float pf = Ds[(8 + jl) * 66 + b]  + Xs[(8 + jl) * 64 + b];
            float pg = Ds[(16 + jl) * 66 + b] + Xs[(16 + jl) * 64 + b];
            float po = Ds[(24 + jl) * 66 + b] + Xs[(24 + jl) * 64 + b];
            float gi = 1.f / (1.f + expf(-pi));
            float gf = 1.f / (1.f + expf(-pf));
            float gg2 = tanhf(pg);
            float go = 1.f / (1.f + expf(-po));
            float c = gf * cst[bl] + gi * gg2;
            cst[bl] = c;
            float h = go * tanhf(c);
            // frag write: k8 = bid, nt = b>>3, gg = b&7, tg = jl&3, half = jl>>2
            float* fp = (float*)(hfout + (bid * 8 + (b >> 3)) * 32 + (b & 7) * 4 + (jl & 3));
            fp[jl >> 2] = f2tf32(h);
            Os[jl * 64 + b] = h;
        }
        __threadfence();
        __syncthreads();

        // ---- arrive ----
        if (tid == 0) {
            unsigned arrived = atomicAdd(&g_bar_count, 1u);
            if (arrived == NBLK - 1) {
                *(volatile unsigned*)&g_bar_count = 0u;
                __threadfence();
                *(volatile unsigned*)&g_bar_epoch = e0 + (unsigned)t + 1u;
            }
        }

        // ---- overlapped tail: seq store + next Xs stage ----
        if (store_seq) {
#pragma unroll
            for (int i = 0; i < 2; i++) {
                int idx = tid + i * 256;
                int jj = idx & 7;
                int b = idx >> 3;
                hs_out[((long)b * Tt + t) * Hh + j0 + jj] = Os[jj * 64 + b];
            }
        } else if (t == Tt - 1) {
#pragma unroll
            for (int i = 0; i < 2; i++) {
                int idx = tid + i * 256;
                int jj = idx & 7;
                int b = idx >> 3;
                hs_out[(long)b * Hh + j0 + jj] = Os[jj * 64 + b];
            }
        }
        if (t + 1 < Tt) {
#pragma unroll
            for (int i = 0; i < 8; i++) {
                int idx = tid + i * 256;
                int jj = idx & 7;
                int gate = (idx >> 3) & 3;
                int b = idx >> 5;
                Xs[(gate * 8 + jj) * 64 + b] =
                    xg[((long)b * Tt + (t + 1)) * G4 + gate * Hh + j0 + jj];
            }
        }

        // ---- wait ----
        if (tid == 0) {
            while (*(volatile unsigned*)&g_bar_epoch < e0 + (unsigned)t + 1u) { }
        }
        __syncthreads();

        const float2* tmp = hfin; hfin = hfout; hfout = (float2*)tmp;
    }
}

// ---------------------------------------------------------------------------
// kernel_launch: 7 graph nodes
// ---------------------------------------------------------------------------
extern "C" void kernel_launch(void* const* d_in, const int* in_sizes, int n_in,
                              void* d_out, int out_size) {
    const float* x     = (const float*)d_in[0];
    const float* W_ih0 = (const float*)d_in[1];
    const float* W_hh0 = (const float*)d_in[2];
    const float* b_ih0 = (const float*)d_in[3];
    const float* b_hh0 = (const float*)d_in[4];
    const float* W_ih1 = (const float*)d_in[5];
    const float* W_hh1 = (const float*)d_in[6];
    const float* b_ih1 = (const float*)d_in[7];
    const float* b_hh1 = (const float*)d_in[8];
    const float* fc_w  = (const float*)d_in[9];
    const float* fc_b  = (const float*)d_in[10];
    float* out = (float*)d_out;

    float *xg, *hs, *hlast;
    float2 *hfA, *hfB;
    cudaGetSymbolAddress((void**)&xg, g_xg);
    cudaGetSymbolAddress((void**)&hs, g_hs);
    cudaGetSymbolAddress((void**)&hfA, g_hfA);
    cudaGetSymbolAddress((void**)&hfB, g_hfB);
    cudaGetSymbolAddress((void**)&hlast, g_hlast);

    const int stateN = Hh * Bb;                       // 65536 floats per buffer
    const int SMEM_PERSIST = SMP_TOT * sizeof(float); // 149,760 B

    static int smem_set = 0;
    if (!smem_set) {
        cudaFuncSetAttribute(lstm_persist_mma2_kernel,
                             cudaFuncAttributeMaxDynamicSharedMemorySize,
                             SMEM_PERSIST);
        smem_set = 1;
    }

    // ---------------- Layer 0 ----------------
    zero2_kernel<<<(stateN + 255) / 256, 256>>>((float*)hfA, (float*)hfB, stateN);

    {   // xg0 = x @ W_ih0^T + b_ih0 + b_hh0
        dim3 grid(G4 / 128, (Bb * Tt) / 128);
        tf32_gemm_bias_kernel<<<grid, 256>>>(x, W_ih0, b_ih0, b_hh0, xg,
                                             Bb * Tt, G4, IN_DIM);
    }

    lstm_persist_mma2_kernel<<<NBLK, 256, SMEM_PERSIST>>>(
        xg, W_hh0, hfA, hfB, hs, 1);

    // ---------------- Layer 1 ----------------
    zero2_kernel<<<(stateN + 255) / 256, 256>>>((float*)hfA, (float*)hfB, stateN);

    {   // xg1 = hs0 @ W_ih1^T + b_ih1 + b_hh1
        dim3 grid(G4 / 128, (Bb * Tt) / 128);
        tf32_gemm_bias_kernel<<<grid, 256>>>(hs, W_ih1, b_ih1, b_hh1, xg,
                                             Bb * Tt, G4, Hh);
    }

    lstm_persist_mma2_kernel<<<NBLK, 256, SMEM_PERSIST>>>(
        xg, W_hh1, hfA, hfB, hlast, 0);

    // ---------------- FC ----------------
    {
        dim3 grid((NCLS + 63) / 64, (Bb + 127) / 128);
        sgemm_bias_kernel<<<grid, 256>>>(hlast, fc_w, fc_b, nullptr, out,
                                         Bb, NCLS, Hh);
    }
}

// round 10
// speedup vs baseline: 5.0670x; 1.3221x over previous
#include <cuda_runtime.h>
#include <cuda_bf16.h>
#include <math.h>
#include <stdint.h>

// Problem dims (fixed)
#define Bb 64
#define Tt 512
#define IN_DIM 512
#define Hh 1024
#define G4 4096
#define NCLS 1000
#define NBLK 128   // persistent grid; single wave on 148 SMs

// Scratch (device globals; no allocation allowed)
__device__ float  g_xg[(size_t)Bb * Tt * G4];
__device__ float  g_hs[(size_t)Bb * Tt * Hh];
// h in bf16 B-fragment layout: uint2 per (kg, nt, lane):
//   .x (b0) = bf16x2 { h[16kg+2tg][b], h[16kg+2tg+1][b] }
//   .y (b1) = bf16x2 { h[16kg+8+2tg][b], h[16kg+8+2tg+1][b] }   b = nt*8+gg
__device__ uint2  g_hfA[64 * 8 * 32];   // ping (128 KB)
__device__ uint2  g_hfB[64 * 8 * 32];   // pong
__device__ float  g_hlast[Bb * Hh];

__device__ unsigned g_bar_count = 0;
__device__ unsigned g_bar_epoch = 0;

// ---------------------------------------------------------------------------
__global__ void zero2_kernel(float* a, float* b, int n) {
    int i = blockIdx.x * blockDim.x + threadIdx.x;
    if (i < n) { a[i] = 0.f; b[i] = 0.f; }
}

// ---------------------------------------------------------------------------
// helpers
// ---------------------------------------------------------------------------
__device__ __forceinline__ float f2tf32(float x) {
    uint32_t u;
    asm("cvt.rna.tf32.f32 %0, %1;" : "=r"(u) : "f"(x));
    return __uint_as_float(u);
}

__device__ __forceinline__ uint32_t pack_bf16x2(float lo, float hi) {
    uint32_t r;
    asm("cvt.rn.bf16x2.f32 %0, %1, %2;" : "=r"(r) : "f"(hi), "f"(lo));
    return r;
}

__device__ __forceinline__ void mma_tf32(float c[4],
                                         uint32_t a0, uint32_t a1, uint32_t a2, uint32_t a3,
                                         uint32_t b0, uint32_t b1) {
    asm volatile(
        "mma.sync.aligned.m16n8k8.row.col.f32.tf32.tf32.f32 "
        "{%0,%1,%2,%3}, {%4,%5,%6,%7}, {%8,%9}, {%0,%1,%2,%3};"
        : "+f"(c[0]), "+f"(c[1]), "+f"(c[2]), "+f"(c[3])
        : "r"(a0), "r"(a1), "r"(a2), "r"(a3), "r"(b0), "r"(b1));
}

__device__ __forceinline__ void mma_bf16(float c[4],
                                         uint32_t a0, uint32_t a1, uint32_t a2, uint32_t a3,
                                         uint32_t b0, uint32_t b1) {
    asm volatile(
        "mma.sync.aligned.m16n8k16.row.col.f32.bf16.bf16.f32 "
        "{%0,%1,%2,%3}, {%4,%5,%6,%7}, {%8,%9}, {%0,%1,%2,%3};"
        : "+f"(c[0]), "+f"(c[1]), "+f"(c[2]), "+f"(c[3])
        : "r"(a0), "r"(a1), "r"(a2), "r"(a3), "r"(b0), "r"(b1));
}

// ---------------------------------------------------------------------------
// tf32 tensor-core GEMM (proven): C = A @ W^T + bias1 + bias2
// REQUIRES: M%128==0, N%128==0, K%32==0.
// ---------------------------------------------------------------------------
__global__ __launch_bounds__(256, 2)
void tf32_gemm_bias_kernel(const float* __restrict__ A,
                           const float* __restrict__ W,
                           const float* __restrict__ bias1,
                           const float* __restrict__ bias2,
                           float* __restrict__ C,
                           int M, int N, int K) {
    __shared__ __align__(16) float As[128 * 36];
    __shared__ __align__(16) float Ws[128 * 36];

    const int tid  = threadIdx.x;
    const int lane = tid & 31;
    const int warp = tid >> 5;
    const int wm = warp >> 2;
    const int wn = warp & 3;
    const int g  = lane >> 2;
    const int tg = lane & 3;

    const long m0 = (long)blockIdx.y * 128;
    const long n0 = (long)blockIdx.x * 128;

    float acc[4][4][4];
#pragma unroll
    for (int i = 0; i < 4; i++)
#pragma unroll
        for (int j = 0; j < 4; j++)
#pragma unroll
            for (int r = 0; r < 4; r++) acc[i][j][r] = 0.f;

    for (int k0 = 0; k0 < K; k0 += 32) {
#pragma unroll
        for (int i = 0; i < 4; i++) {
            int idx = tid + i * 256;
            int r = idx >> 3;
            int c4 = (idx & 7) * 4;
            float4 va = *(const float4*)&A[(m0 + r) * K + k0 + c4];
            float4 vw = *(const float4*)&W[(n0 + r) * K + k0 + c4];
            va.x = f2tf32(va.x); va.y = f2tf32(va.y); va.z = f2tf32(va.z); va.w = f2tf32(va.w);
            vw.x = f2tf32(vw.x); vw.y = f2tf32(vw.y); vw.z = f2tf32(vw.z); vw.w = f2tf32(vw.w);
            *(float4*)&As[r * 36 + c4] = va;
            *(float4*)&Ws[r * 36 + c4] = vw;
        }
        __syncthreads();

#pragma unroll
        for (int k8 = 0; k8 < 4; k8++) {
            const int kb = k8 * 8;
            uint32_t af[4][4];
#pragma unroll
            for (int mt = 0; mt < 4; mt++) {
                const float* ab = &As[(wm * 64 + mt * 16 + g) * 36 + kb + tg];
                af[mt][0] = __float_as_uint(ab[0]);
                af[mt][2] = __float_as_uint(ab[4]);
                af[mt][1] = __float_as_uint(ab[8 * 36]);
                af[mt][3] = __float_as_uint(ab[8 * 36 + 4]);
            }
            uint32_t bf[4][2];
#pragma unroll
            for (int nt = 0; nt < 4; nt++) {
                const float* bb = &Ws[(wn * 32 + nt * 8 + g) * 36 + kb + tg];
                bf[nt][0] = __float_as_uint(bb[0]);
                bf[nt][1] = __float_as_uint(bb[4]);
            }
#pragma unroll
            for (int mt = 0; mt < 4; mt++)
#pragma unroll
                for (int nt = 0; nt < 4; nt++)
                    mma_tf32(acc[mt][nt], af[mt][0], af[mt][1], af[mt][2], af[mt][3],
                             bf[nt][0], bf[nt][1]);
        }
        __syncthreads();
    }

#pragma unroll
    for (int mt = 0; mt < 4; mt++) {
#pragma unroll
        for (int nt = 0; nt < 4; nt++) {
            long row0 = m0 + wm * 64 + mt * 16 + g;
            long col  = n0 + wn * 32 + nt * 8 + tg * 2;
            float bsum0 = (bias1 ? bias1[col]     : 0.f) + (bias2 ? bias2[col]     : 0.f);
            float bsum1 = (bias1 ? bias1[col + 1] : 0.f) + (bias2 ? bias2[col + 1] : 0.f);
            float2 v0 = make_float2(acc[mt][nt][0] + bsum0, acc[mt][nt][1] + bsum1);
            float2 v1 = make_float2(acc[mt][nt][2] + bsum0, acc[mt][nt][3] + bsum1);
            *(float2*)&C[row0 * N + col] = v0;
            *(float2*)&C[(row0 + 8) * N + col] = v1;
        }
    }
}

// ---------------------------------------------------------------------------
// fp32 SGEMM (FC only)
// ---------------------------------------------------------------------------
__global__ void sgemm_bias_kernel(const float* __restrict__ A,
                                  const float* __restrict__ W,
                                  const float* __restrict__ bias1,
                                  const float* __restrict__ bias2,
                                  float* __restrict__ C,
                                  int M, int N, int K) {
    __shared__ __align__(16) float As[16 * 132];
    __shared__ __align__(16) float Ws[16 * 68];
    const int m0 = blockIdx.y * 128;
    const int n0 = blockIdx.x * 64;
    const int tid = threadIdx.x;
    const int tx = tid & 15;
    const int ty = tid >> 4;
    float acc[8][4] = {};

    for (int k0 = 0; k0 < K; k0 += 16) {
#pragma unroll
        for (int i = 0; i < 8; i++) {
            int idx = tid + i * 256;
            int k = idx & 15;
            int r = idx >> 4;
            As[k * 132 + r] = (m0 + r < M) ? A[(long)(m0 + r) * K + k0 + k] : 0.f;
        }
#pragma unroll
        for (int i = 0; i < 4; i++) {
            int idx = tid + i * 256;
            int k = idx & 15;
            int r = idx >> 4;
            Ws[k * 68 + r] = (n0 + r < N) ? W[(long)(n0 + r) * K + k0 + k] : 0.f;
        }
        __syncthreads();
#pragma unroll
        for (int kk = 0; kk < 16; kk++) {
            float4 b = *(const float4*)&Ws[kk * 68 + tx * 4];
            float4 a0 = *(const float4*)&As[kk * 132 + ty * 8];
            float4 a1 = *(const float4*)&As[kk * 132 + ty * 8 + 4];
            acc[0][0] += a0.x * b.x; acc[0][1] += a0.x * b.y; acc[0][2] += a0.x * b.z; acc[0][3] += a0.x * b.w;
            acc[1][0] += a0.y * b.x; acc[1][1] += a0.y * b.y; acc[1][2] += a0.y * b.z; acc[1][3] += a0.y * b.w;
            acc[2][0] += a0.z * b.x; acc[2][1] += a0.z * b.y; acc[2][2] += a0.z * b.z; acc[2][3] += a0.z * b.w;
            acc[3][0] += a0.w * b.x; acc[3][1] += a0.w * b.y; acc[3][2] += a0.w * b.z; acc[3][3] += a0.w * b.w;
            acc[4][0] += a1.x * b.x; acc[4][1] += a1.x * b.y; acc[4][2] += a1.x * b.z; acc[4][3] += a1.x * b.w;
            acc[5][0] += a1.y * b.x; acc[5][1] += a1.y * b.y; acc[5][2] += a1.y * b.z; acc[5][3] += a1.y * b.w;
            acc[6][0] += a1.z * b.x; acc[6][1] += a1.z * b.y; acc[6][2] += a1.z * b.z; acc[6][3] += a1.z * b.w;
            acc[7][0] += a1.w * b.x; acc[7][1] += a1.w * b.y; acc[7][2] += a1.w * b.z; acc[7][3] += a1.w * b.w;
        }
        __syncthreads();
    }

#pragma unroll
    for (int i = 0; i < 8; i++) {
        int m = m0 + ty * 8 + i;
        if (m >= M) continue;
#pragma unroll
        for (int j = 0; j < 4; j++) {
            int n = n0 + tx * 4 + j;
            if (n >= N) continue;
            float bsum = (bias1 ? bias1[n] : 0.f) + (bias2 ? bias2[n] : 0.f);
            C[(long)m * N + n] = acc[i][j] + bsum;
        }
    }
}

// ---------------------------------------------------------------------------
// Persistent LSTM, bf16 mma (m16n8k16), h exchanged in bf16 B-frag layout.
// Block bid owns j = 8*bid..8*bid+7 (gate rows 0..31), kg = bid>>1.
// Block pair (2m, 2m+1) co-produces k-group m: even block fills .x (b0),
// odd block fills .y (b1) of each uint2 — disjoint bytes.
// smem (floats): Wfrag 16384 | Ds 2112 | Xs 2048 | Os 512 = 21056 f (84,224 B)
// ---------------------------------------------------------------------------
#define SMP_DS 16384
#define SMP_XS (SMP_DS + 2112)
#define SMP_OS (SMP_XS + 2048)
#define SMP_TOT (SMP_OS + 512)

__global__ __launch_bounds__(256, 1)
void lstm_persist_bf16_kernel(const float* __restrict__ xg,
                              const float* __restrict__ W_hh,
                              uint2* hfA, uint2* hfB,
                              float* __restrict__ hs_out,
                              int store_seq) {
    extern __shared__ float smem[];
    uint4* Wfrag = (uint4*)smem;            // [mt*64 + kg][lane] -> {a0,a1,a2,a3}
    float* Ds = smem + SMP_DS;
    float* Xs = smem + SMP_XS;
    float* Os = smem + SMP_OS;

    const int tid  = threadIdx.x;      // 256
    const int lane = tid & 31;
    const int w    = tid >> 5;         // warp == nt == jl
    const int g    = lane >> 2;
    const int tg   = lane & 3;
    const int bid  = blockIdx.x;
    const int j0   = bid * 8;
    const int bp   = lane;
    const int jl   = w;

    __shared__ unsigned s_e0;
    if (tid == 0) s_e0 = *(volatile unsigned*)&g_bar_epoch;
    __syncthreads();
    const unsigned e0 = s_e0;

    // ---- one-time: W_hh -> bf16 A-fragment smem ----
    for (int i = tid; i < 4096; i += 256) {
        int l   = i & 31;
        int grp = i >> 5;              // 0..127
        int kg  = grp & 63;
        int mtl = grp >> 6;
        int gg = l >> 2, tt = l & 3;
        int r0 = mtl * 16 + gg;
        int r1 = r0 + 8;
        long row0 = (long)((r0 >> 3) * Hh + j0 + (r0 & 7)) * Hh;
        long row1 = (long)((r1 >> 3) * Hh + j0 + (r1 & 7)) * Hh;
        int k0 = kg * 16 + 2 * tt;
        int kh = k0 + 8;
        uint4 v;
        v.x = pack_bf16x2(W_hh[row0 + k0], W_hh[row0 + k0 + 1]);
        v.y = pack_bf16x2(W_hh[row1 + k0], W_hh[row1 + k0 + 1]);
        v.z = pack_bf16x2(W_hh[row0 + kh], W_hh[row0 + kh + 1]);
        v.w = pack_bf16x2(W_hh[row1 + kh], W_hh[row1 + kh + 1]);
        Wfrag[i] = v;
    }

    // producer write geometry: jj16 = position of j within its k16 group
    const int jj16 = ((bid & 1) << 3) + jl;
    const int tgp  = (jj16 & 7) >> 1;                        // tg slot
    const int bsub = ((jj16 >= 8) ? 4 : 0) + (jj16 & 1) * 2; // byte offset in uint2
    const int kgp  = bid >> 1;                               // this block's k-group

    float cst[2] = {0.f, 0.f};
    const uint2* hfin = hfA;
    uint2* hfout = hfB;
    __syncthreads();

    // stage Xs for t=0
#pragma unroll
    for (int i = 0; i < 8; i++) {
        int idx = tid + i * 256;
        int jj = idx & 7;
        int gate = (idx >> 3) & 3;
        int b = idx >> 5;
        Xs[(gate * 8 + jj) * 64 + b] =
            xg[((long)b * Tt + 0) * G4 + gate * Hh + j0 + jj];
    }

    for (int t = 0; t < Tt; t++) {
        float acc0[4] = {0.f, 0.f, 0.f, 0.f};   // rows 0..15
        float acc1[4] = {0.f, 0.f, 0.f, 0.f};   // rows 16..31

        // ---- mma loop over 64 k16-groups; B from global frags, A from smem ----
        const uint2* hbase = hfin + w * 32 + lane;    // + kg*256
        uint2 Bq[8];
#pragma unroll
        for (int p = 0; p < 8; p++) Bq[p] = __ldcg(hbase + p * 256);
        uint4 A0n = Wfrag[lane];
        uint4 A1n = Wfrag[64 * 32 + lane];

#pragma unroll 8
        for (int kg = 0; kg < 64; kg++) {
            uint4 A0 = A0n, A1 = A1n;
            uint2 B  = Bq[kg & 7];
            if (kg < 63) {
                A0n = Wfrag[(kg + 1) * 32 + lane];
                A1n = Wfrag[(64 + kg + 1) * 32 + lane];
            }
            if (kg + 8 < 64) Bq[kg & 7] = __ldcg(hbase + (kg + 8) * 256);
            mma_bf16(acc0, A0.x, A0.y, A0.z, A0.w, B.x, B.y);
            mma_bf16(acc1, A1.x, A1.y, A1.z, A1.w, B.x, B.y);
        }

        // ---- D scatter ----
        {
            int c0 = w * 8 + tg * 2;
            Ds[g * 66 + c0]            = acc0[0];
            Ds[g * 66 + c0 + 1]        = acc0[1];
            Ds[(g + 8) * 66 + c0]      = acc0[2];
            Ds[(g + 8) * 66 + c0 + 1]  = acc0[3];
            Ds[(16 + g) * 66 + c0]     = acc1[0];
            Ds[(16 + g) * 66 + c0 + 1] = acc1[1];
            Ds[(24 + g) * 66 + c0]     = acc1[2];
            Ds[(24 + g) * 66 + c0 + 1] = acc1[3];
        }
        __syncthreads();

        // ---- pointwise LSTM; h -> bf16 frag buffer + Os ----
#pragma unroll
        for (int bl = 0; bl < 2; bl++) {
            int b = bp * 2 + bl;
            float pi = Ds[jl * 66 + b]        + Xs[jl * 64 + b];
            float pf = Ds[(8 + jl) * 66 + b]  + Xs[(8 + jl) * 64 + b];
            float pg = Ds[(16 + jl) * 66 + b] + Xs[(16 + jl) * 64 + b];
            float po = Ds[(24 + jl) * 66 + b] + Xs[(24 + jl) * 64 + b];
            float gi = 1.f / (1.f + expf(-pi));
            float gf = 1.f / (1.f + expf(-pf));
            float gg2 = tanhf(pg);
            float go = 1.f / (1.f + expf(-po));
            float c = gf * cst[bl] + gi * gg2;
            cst[bl] = c;
            float h = go * tanhf(c);
            // frag write: uint2 index = (kgp*8 + b>>3)*32 + (b&7)*4 + tgp
            char* fp = (char*)(hfout + ((kgp * 8 + (b >> 3)) * 32 + (b & 7) * 4 + tgp)) + bsub;
            *(__nv_bfloat16*)fp = __float2bfloat16_rn(h);
            Os[jl * 64 + b] = h;
        }
        __threadfence();
        __syncthreads();

        // ---- arrive ----
        if (tid == 0) {
            unsigned arrived = atomicAdd(&g_bar_count, 1u);
            if (arrived == NBLK - 1) {
                *(volatile unsigned*)&g_bar_count = 0u;
                __threadfence();
                *(volatile unsigned*)&g_bar_epoch = e0 + (unsigned)t + 1u;
            }
        }

        // ---- overlapped tail: seq store + next Xs stage ----
        if (store_seq) {
#pragma unroll
            for (int i = 0; i < 2; i++) {
                int idx = tid + i * 256;
                int jj = idx & 7;
                int b = idx >> 3;
                hs_out[((long)b * Tt + t) * Hh + j0 + jj] = Os[jj * 64 + b];
            }
        } else if (t == Tt - 1) {
#pragma unroll
            for (int i = 0; i < 2; i++) {
                int idx = tid + i * 256;
                int jj = idx & 7;
                int b = idx >> 3;
                hs_out[(long)b * Hh + j0 + jj] = Os[jj * 64 + b];
            }
        }
        if (t + 1 < Tt) {
#pragma unroll
            for (int i = 0; i < 8; i++) {
                int idx = tid + i * 256;
                int jj = idx & 7;
                int gate = (idx >> 3) & 3;
                int b = idx >> 5;
                Xs[(gate * 8 + jj) * 64 + b] =
                    xg[((long)b * Tt + (t + 1)) * G4 + gate * Hh + j0 + jj];
            }
        }

        // ---- wait ----
        if (tid == 0) {
            while (*(volatile unsigned*)&g_bar_epoch < e0 + (unsigned)t + 1u) { }
        }
        __syncthreads();

        const uint2* tmp = hfin; hfin = hfout; hfout = (uint2*)tmp;
    }
}

// ---------------------------------------------------------------------------
// kernel_launch: 7 graph nodes
// ---------------------------------------------------------------------------
extern "C" void kernel_launch(void* const* d_in, const int* in_sizes, int n_in,
                              void* d_out, int out_size) {
    const float* x     = (const float*)d_in[0];
    const float* W_ih0 = (const float*)d_in[1];
    const float* W_hh0 = (const float*)d_in[2];
    const float* b_ih0 = (const float*)d_in[3];
    const float* b_hh0 = (const float*)d_in[4];
    const float* W_ih1 = (const float*)d_in[5];
    const float* W_hh1 = (const float*)d_in[6];
    const float* b_ih1 = (const float*)d_in[7];
    const float* b_hh1 = (const float*)d_in[8];
    const float* fc_w  = (const float*)d_in[9];
    const float* fc_b  = (const float*)d_in[10];
    float* out = (float*)d_out;

    float *xg, *hs, *hlast;
    uint2 *hfA, *hfB;
    cudaGetSymbolAddress((void**)&xg, g_xg);
    cudaGetSymbolAddress((void**)&hs, g_hs);
    cudaGetSymbolAddress((void**)&hfA, g_hfA);
    cudaGetSymbolAddress((void**)&hfB, g_hfB);
    cudaGetSymbolAddress((void**)&hlast, g_hlast);

    const int fragN = 64 * 8 * 32 * 2;                // uint32 per frag buffer
    const int SMEM_PERSIST = SMP_TOT * sizeof(float); // 84,224 B

    static int smem_set = 0;
    if (!smem_set) {
        cudaFuncSetAttribute(lstm_persist_bf16_kernel,
                             cudaFuncAttributeMaxDynamicSharedMemorySize,
                             SMEM_PERSIST);
        smem_set = 1;
    }

    // ---------------- Layer 0 ----------------
    zero2_kernel<<<(fragN + 255) / 256, 256>>>((float*)hfA, (float*)hfB, fragN);

    {   // xg0 = x @ W_ih0^T + b_ih0 + b_hh0
        dim3 grid(G4 / 128, (Bb * Tt) / 128);
        tf32_gemm_bias_kernel<<<grid, 256>>>(x, W_ih0, b_ih0, b_hh0, xg,
                                             Bb * Tt, G4, IN_DIM);
    }

    lstm_persist_bf16_kernel<<<NBLK, 256, SMEM_PERSIST>>>(
        xg, W_hh0, hfA, hfB, hs, 1);

    // ---------------- Layer 1 ----------------
    zero2_kernel<<<(fragN + 255) / 256, 256>>>((float*)hfA, (float*)hfB, fragN);

    {   // xg1 = hs0 @ W_ih1^T + b_ih1 + b_hh1
        dim3 grid(G4 / 128, (Bb * Tt) / 128);
        tf32_gemm_bias_kernel<<<grid, 256>>>(hs, W_ih1, b_ih1, b_hh1, xg,
                                             Bb * Tt, G4, Hh);
    }

    lstm_persist_bf16_kernel<<<NBLK, 256, SMEM_PERSIST>>>(
        xg, W_hh1, hfA, hfB, hlast, 0);

    // ---------------- FC ----------------
    {
        dim3 grid((NCLS + 63) / 64, (Bb + 127) / 128);
        sgemm_bias_kernel<<<grid, 256>>>(hlast, fc_w, fc_b, nullptr, out,
                                         Bb, NCLS, Hh);
    }
}

// round 11
// speedup vs baseline: 5.5016x; 1.0858x over previous
#include <cuda_runtime.h>
#include <cuda_bf16.h>
#include <math.h>
#include <stdint.h>

// Problem dims (fixed)
#define Bb 64
#define Tt 512
#define IN_DIM 512
#define Hh 1024
#define G4 4096
#define NCLS 1000
#define NBLK 128   // persistent grid; single wave on 148 SMs

// Scratch (device globals; no allocation allowed)
__device__ float  g_xg[(size_t)Bb * Tt * G4];
__device__ float  g_hs[(size_t)Bb * Tt * Hh];
// h in bf16 B-fragment layout: uint2 per (kg, nt, lane)
__device__ uint2  g_hfA[64 * 8 * 32];   // ping (128 KB)
__device__ uint2  g_hfB[64 * 8 * 32];   // pong
__device__ float  g_hlast[Bb * Hh];

__device__ unsigned g_bar_count = 0;
__device__ unsigned g_bar_epoch = 0;

// ---------------------------------------------------------------------------
__global__ void zero2_kernel(float* a, float* b, int n) {
    int i = blockIdx.x * blockDim.x + threadIdx.x;
    if (i < n) { a[i] = 0.f; b[i] = 0.f; }
}

// ---------------------------------------------------------------------------
// helpers
// ---------------------------------------------------------------------------
__device__ __forceinline__ uint32_t f2tf32u(float x) {
    uint32_t u;
    asm("cvt.rna.tf32.f32 %0, %1;" : "=r"(u) : "f"(x));
    return u;
}

__device__ __forceinline__ uint32_t pack_bf16x2(float lo, float hi) {
    uint32_t r;
    asm("cvt.rn.bf16x2.f32 %0, %1, %2;" : "=r"(r) : "f"(hi), "f"(lo));
    return r;
}

__device__ __forceinline__ void mma_tf32(float c[4],
                                         uint32_t a0, uint32_t a1, uint32_t a2, uint32_t a3,
                                         uint32_t b0, uint32_t b1) {
    asm volatile(
        "mma.sync.aligned.m16n8k8.row.col.f32.tf32.tf32.f32 "
        "{%0,%1,%2,%3}, {%4,%5,%6,%7}, {%8,%9}, {%0,%1,%2,%3};"
        : "+f"(c[0]), "+f"(c[1]), "+f"(c[2]), "+f"(c[3])
        : "r"(a0), "r"(a1), "r"(a2), "r"(a3), "r"(b0), "r"(b1));
}

__device__ __forceinline__ void mma_bf16(float c[4],
                                         uint32_t a0, uint32_t a1, uint32_t a2, uint32_t a3,
                                         uint32_t b0, uint32_t b1) {
    asm volatile(
        "mma.sync.aligned.m16n8k16.row.col.f32.bf16.bf16.f32 "
        "{%0,%1,%2,%3}, {%4,%5,%6,%7}, {%8,%9}, {%0,%1,%2,%3};"
        : "+f"(c[0]), "+f"(c[1]), "+f"(c[2]), "+f"(c[3])
        : "r"(a0), "r"(a1), "r"(a2), "r"(a3), "r"(b0), "r"(b1));
}

__device__ __forceinline__ uint32_t smem_u32(const void* p) {
    uint32_t a;
    asm("{ .reg .u64 t; cvta.to.shared.u64 t, %1; cvt.u32.u64 %0, t; }"
        : "=r"(a) : "l"(p));
    return a;
}

__device__ __forceinline__ void cp16(uint32_t dst, const void* src) {
    asm volatile("cp.async.cg.shared.global [%0], [%1], 16;" :: "r"(dst), "l"(src));
}

// ---------------------------------------------------------------------------
// tf32 GEMM v2: cp.async double-buffered. C = A @ W^T + bias1 + bias2
// REQUIRES: M%128==0, N%128==0, K%32==0. Same fragment math as proven v1;
// tf32 rounding moved to fragment load (bit-identical results).
// dynamic smem: As0|Ws0|As1|Ws1, each 128*36 floats = 73,728 B total
// ---------------------------------------------------------------------------
__global__ __launch_bounds__(256, 2)
void tf32_gemm_async_kernel(const float* __restrict__ A,
                            const float* __restrict__ W,
                            const float* __restrict__ bias1,
                            const float* __restrict__ bias2,
                            float* __restrict__ C,
                            int M, int N, int K) {
    extern __shared__ float gsm[];
    float* Abuf[2] = { gsm,            gsm + 9216  };
    float* Wbuf[2] = { gsm + 4608,     gsm + 13824 };

    const int tid  = threadIdx.x;
    const int lane = tid & 31;
    const int warp = tid >> 5;
    const int wm = warp >> 2;
    const int wn = warp & 3;
    const int g  = lane >> 2;
    const int tg = lane & 3;

    const long m0 = (long)blockIdx.y * 128;
    const long n0 = (long)blockIdx.x * 128;
    const int ntiles = K >> 5;

    float acc[4][4][4];
#pragma unroll
    for (int i = 0; i < 4; i++)
#pragma unroll
        for (int j = 0; j < 4; j++)
#pragma unroll
            for (int r = 0; r < 4; r++) acc[i][j][r] = 0.f;

    // stage lambda: raw floats, no cvt
    auto stage = [&](int tile, int buf) {
        const long k0 = (long)tile * 32;
        uint32_t sa = smem_u32(Abuf[buf]);
        uint32_t sw = smem_u32(Wbuf[buf]);
#pragma unroll
        for (int i = 0; i < 4; i++) {
            int idx = tid + i * 256;
            int r = idx >> 3;
            int c4 = (idx & 7) * 4;
            uint32_t off = (uint32_t)(r * 36 + c4) * 4u;
            cp16(sa + off, &A[(m0 + r) * K + k0 + c4]);
            cp16(sw + off, &W[(n0 + r) * K + k0 + c4]);
        }
        asm volatile("cp.async.commit_group;");
    };

    stage(0, 0);
    stage(1, 1);

    for (int t = 0; t < ntiles; t++) {
        const int buf = t & 1;
        asm volatile("cp.async.wait_group 1;");
        __syncthreads();

        const float* As = Abuf[buf];
        const float* Ws = Wbuf[buf];
#pragma unroll
        for (int k8 = 0; k8 < 4; k8++) {
            const int kb = k8 * 8;
            uint32_t af[4][4];
#pragma unroll
            for (int mt = 0; mt < 4; mt++) {
                const float* ab = &As[(wm * 64 + mt * 16 + g) * 36 + kb + tg];
                af[mt][0] = f2tf32u(ab[0]);
                af[mt][2] = f2tf32u(ab[4]);
                af[mt][1] = f2tf32u(ab[8 * 36]);
                af[mt][3] = f2tf32u(ab[8 * 36 + 4]);
            }
            uint32_t bf[4][2];
#pragma unroll
            for (int nt = 0; nt < 4; nt++) {
                const float* bb = &Ws[(wn * 32 + nt * 8 + g) * 36 + kb + tg];
                bf[nt][0] = f2tf32u(bb[0]);
                bf[nt][1] = f2tf32u(bb[4]);
            }
#pragma unroll
            for (int mt = 0; mt < 4; mt++)
#pragma unroll
                for (int nt = 0; nt < 4; nt++)
                    mma_tf32(acc[mt][nt], af[mt][0], af[mt][1], af[mt][2], af[mt][3],
                             bf[nt][0], bf[nt][1]);
        }
        __syncthreads();
        if (t + 2 < ntiles) stage(t + 2, buf);
    }

#pragma unroll
    for (int mt = 0; mt < 4; mt++) {
#pragma unroll
        for (int nt = 0; nt < 4; nt++) {
            long row0 = m0 + wm * 64 + mt * 16 + g;
            long col  = n0 + wn * 32 + nt * 8 + tg * 2;
            float bsum0 = (bias1 ? bias1[col]     : 0.f) + (bias2 ? bias2[col]     : 0.f);
            float bsum1 = (bias1 ? bias1[col + 1] : 0.f) + (bias2 ? bias2[col + 1] : 0.f);
            float2 v0 = make_float2(acc[mt][nt][0] + bsum0, acc[mt][nt][1] + bsum1);
            float2 v1 = make_float2(acc[mt][nt][2] + bsum0, acc[mt][nt][3] + bsum1);
            *(float2*)&C[row0 * N + col] = v0;
            *(float2*)&C[(row0 + 8) * N + col] = v1;
        }
    }
}

// ---------------------------------------------------------------------------
// fp32 SGEMM (FC only)
// ---------------------------------------------------------------------------
__global__ void sgemm_bias_kernel(const float* __restrict__ A,
                                  const float* __restrict__ W,
                                  const float* __restrict__ bias1,
                                  const float* __restrict__ bias2,
                                  float* __restrict__ C,
                                  int M, int N, int K) {
    __shared__ __align__(16) float As[16 * 132];
    __shared__ __align__(16) float Ws[16 * 68];
    const int m0 = blockIdx.y * 128;
    const int n0 = blockIdx.x * 64;
    const int tid = threadIdx.x;
    const int tx = tid & 15;
    const int ty = tid >> 4;
    float acc[8][4] = {};

    for (int k0 = 0; k0 < K; k0 += 16) {
#pragma unroll
        for (int i = 0; i < 8; i++) {
            int idx = tid + i * 256;
            int k = idx & 15;
            int r = idx >> 4;
            As[k * 132 + r] = (m0 + r < M) ? A[(long)(m0 + r) * K + k0 + k] : 0.f;
        }
#pragma unroll
        for (int i = 0; i < 4; i++) {
            int idx = tid + i * 256;
            int k = idx & 15;
            int r = idx >> 4;
            Ws[k * 68 + r] = (n0 + r < N) ? W[(long)(n0 + r) * K + k0 + k] : 0.f;
        }
        __syncthreads();
#pragma unroll
        for (int kk = 0; kk < 16; kk++) {
            float4 b = *(const float4*)&Ws[kk * 68 + tx * 4];
            float4 a0 = *(const float4*)&As[kk * 132 + ty * 8];
            float4 a1 = *(const float4*)&As[kk * 132 + ty * 8 + 4];
            acc[0][0] += a0.x * b.x; acc[0][1] += a0.x * b.y; acc[0][2] += a0.x * b.z; acc[0][3] += a0.x * b.w;
            acc[1][0] += a0.y * b.x; acc[1][1] += a0.y * b.y; acc[1][2] += a0.y * b.z; acc[1][3] += a0.y * b.w;
            acc[2][0] += a0.z * b.x; acc[2][1] += a0.z * b.y; acc[2][2] += a0.z * b.z; acc[2][3] += a0.z * b.w;
            acc[3][0] += a0.w * b.x; acc[3][1] += a0.w * b.y; acc[3][2] += a0.w * b.z; acc[3][3] += a0.w * b.w;
            acc[4][0] += a1.x * b.x; acc[4][1] += a1.x * b.y; acc[4][2] += a1.x * b.z; acc[4][3] += a1.x * b.w;
            acc[5][0] += a1.y * b.x; acc[5][1] += a1.y * b.y; acc[5][2] += a1.y * b.z; acc[5][3] += a1.y * b.w;
            acc[6][0] += a1.z * b.x; acc[6][1] += a1.z * b.y; acc[6][2] += a1.z * b.z; acc[6][3] += a1.z * b.w;
            acc[7][0] += a1.w * b.x; acc[7][1] += a1.w * b.y; acc[7][2] += a1.w * b.z; acc[7][3] += a1.w * b.w;
        }
        __syncthreads();
    }

#pragma unroll
    for (int i = 0; i < 8; i++) {
        int m = m0 + ty * 8 + i;
        if (m >= M) continue;
#pragma unroll
        for (int j = 0; j < 4; j++) {
            int n = n0 + tx * 4 + j;
            if (n >= N) continue;
            float bsum = (bias1 ? bias1[n] : 0.f) + (bias2 ? bias2[n] : 0.f);
            C[(long)m * N + n] = acc[i][j] + bsum;
        }
    }
}

// ---------------------------------------------------------------------------
// Persistent LSTM v3: k-split warps, W fragments in REGISTERS (loaded once),
// bf16 m16n8k16 mma, B from global frag buffer, cross-warp k-reduction in smem.
// Warp w owns kg in [8w, 8w+8), both m-tiles, all 8 n-tiles.
// smem (floats): Ps 8*32*68=17408 | Ds 32*68=2176 | Xs 2048 | Os 512 = 22144
// ---------------------------------------------------------------------------
#define SMP_PS 0
#define SMP_DS 17408
#define SMP_XS (SMP_DS + 2176)
#define SMP_OS (SMP_XS + 2048)
#define SMP_TOT (SMP_OS + 512)   // 22144 floats = 88,576 B

__global__ __launch_bounds__(256, 1)
void lstm_persist_bf16_kernel(const float* __restrict__ xg,
                              const float* __restrict__ W_hh,
                              uint2* hfA, uint2* hfB,
                              float* __restrict__ hs_out,
                              int store_seq) {
    extern __shared__ float smem[];
    float* Ps = smem + SMP_PS;
    float* Ds = smem + SMP_DS;
    float* Xs = smem + SMP_XS;
    float* Os = smem + SMP_OS;

    const int tid  = threadIdx.x;      // 256
    const int lane = tid & 31;
    const int w    = tid >> 5;         // warp 0..7: k-slice owner; also jl for pointwise
    const int g    = lane >> 2;
    const int tg   = lane & 3;
    const int bid  = blockIdx.x;
    const int j0   = bid * 8;
    const int bp   = lane;
    const int jl   = w;

    __shared__ unsigned s_e0;
    if (tid == 0) s_e0 = *(volatile unsigned*)&g_bar_epoch;
    __syncthreads();
    const unsigned e0 = s_e0;

    // ---- one-time: this warp's W fragments -> REGISTERS (time-invariant) ----
    // af0[kgl] = rows (g, g+8)       [gates 0..1 region rows 0..15]
    // af1[kgl] = rows (16+g, 24+g)   [rows 16..31]
    uint4 af0[8], af1[8];
#pragma unroll
    for (int kgl = 0; kgl < 8; kgl++) {
        int kg = w * 8 + kgl;
        int k0 = kg * 16 + 2 * tg;
        int kh = k0 + 8;
        int r;
        long rowA, rowB;
        // mt = 0
        r = g;       rowA = (long)((r >> 3) * Hh + j0 + (r & 7)) * Hh;
        r = g + 8;   rowB = (long)((r >> 3) * Hh + j0 + (r & 7)) * Hh;
        af0[kgl].x = pack_bf16x2(W_hh[rowA + k0], W_hh[rowA + k0 + 1]);
        af0[kgl].y = pack_bf16x2(W_hh[rowB + k0], W_hh[rowB + k0 + 1]);
        af0[kgl].z = pack_bf16x2(W_hh[rowA + kh], W_hh[rowA + kh + 1]);
        af0[kgl].w = pack_bf16x2(W_hh[rowB + kh], W_hh[rowB + kh + 1]);
        // mt = 1
        r = 16 + g;  rowA = (long)((r >> 3) * Hh + j0 + (r & 7)) * Hh;
        r = 24 + g;  rowB = (long)((r >> 3) * Hh + j0 + (r & 7)) * Hh;
        af1[kgl].x = pack_bf16x2(W_hh[rowA + k0], W_hh[rowA + k0 + 1]);
        af1[kgl].y = pack_bf16x2(W_hh[rowB + k0], W_hh[rowB + k0 + 1]);
        af1[kgl].z = pack_bf16x2(W_hh[rowA + kh], W_hh[rowA + kh + 1]);
        af1[kgl].w = pack_bf16x2(W_hh[rowB + kh], W_hh[rowB + kh + 1]);
    }

    // producer write geometry (same proven mapping as R10)
    const int jj16 = ((bid & 1) << 3) + jl;
    const int tgp  = (jj16 & 7) >> 1;
    const int bsub = ((jj16 >= 8) ? 4 : 0) + (jj16 & 1) * 2;
    const int kgp  = bid >> 1;

    float cst[2] = {0.f, 0.f};
    const uint2* hfin = hfA;
    uint2* hfout = hfB;
    __syncthreads();

    // stage Xs for t=0
#pragma unroll
    for (int i = 0; i < 8; i++) {
        int idx = tid + i * 256;
        int jj = idx & 7;
        int gate = (idx >> 3) & 3;
        int b = idx >> 5;
        Xs[(gate * 8 + jj) * 64 + b] =
            xg[((long)b * Tt + 0) * G4 + gate * Hh + j0 + jj];
    }

    for (int t = 0; t < Tt; t++) {
        float acc0[8][4], acc1[8][4];
#pragma unroll
        for (int nt = 0; nt < 8; nt++)
#pragma unroll
            for (int r = 0; r < 4; r++) { acc0[nt][r] = 0.f; acc1[nt][r] = 0.f; }

        // ---- mma over this warp's 8 k16-groups x 8 n-tiles; B from L2 ----
        const uint2* hb = hfin + (w * 64) * 32 + lane;   // i = kgl*8+nt -> +i*32
        uint2 Bq[8];
#pragma unroll
        for (int p = 0; p < 8; p++) Bq[p] = __ldcg(hb + p * 32);

#pragma unroll
        for (int i = 0; i < 64; i++) {
            uint2 B = Bq[i & 7];
            if (i + 8 < 64) Bq[i & 7] = __ldcg(hb + (i + 8) * 32);
            const int kgl = i >> 3;
            const int nt  = i & 7;
            mma_bf16(acc0[nt], af0[kgl].x, af0[kgl].y, af0[kgl].z, af0[kgl].w, B.x, B.y);
            mma_bf16(acc1[nt], af1[kgl].x, af1[kgl].y, af1[kgl].z, af1[kgl].w, B.x, B.y);
        }

        // ---- store k-partials ----
        {
            float* myPs = Ps + w * 2176;   // 32*68
#pragma unroll
            for (int nt = 0; nt < 8; nt++) {
                int c0 = nt * 8 + tg * 2;
                *(float2*)&myPs[g * 68 + c0]        = make_float2(acc0[nt][0], acc0[nt][1]);
                *(float2*)&myPs[(g + 8) * 68 + c0]  = make_float2(acc0[nt][2], acc0[nt][3]);
                *(float2*)&myPs[(16 + g) * 68 + c0] = make_float2(acc1[nt][0], acc1[nt][1]);
                *(float2*)&myPs[(24 + g) * 68 + c0] = make_float2(acc1[nt][2], acc1[nt][3]);
            }
        }
        __syncthreads();

        // ---- reduce 8 partials -> Ds[row*68 + col] ----
        {
            int row  = tid >> 3;             // 0..31
            int col0 = (tid & 7) * 8;        // 0,8,..56
            float4 s0 = make_float4(0.f, 0.f, 0.f, 0.f);
            float4 s1 = make_float4(0.f, 0.f, 0.f, 0.f);
#pragma unroll
            for (int ww = 0; ww < 8; ww++) {
                const float* p = Ps + ww * 2176 + row * 68 + col0;
                float4 a = *(const float4*)p;
                float4 b = *(const float4*)(p + 4);
                s0.x += a.x; s0.y += a.y; s0.z += a.z; s0.w += a.w;
                s1.x += b.x; s1.y += b.y; s1.z += b.z; s1.w += b.w;
            }
            *(float4*)&Ds[row * 68 + col0]     = s0;
            *(float4*)&Ds[row * 68 + col0 + 4] = s1;
        }
        __syncthreads();

        // ---- pointwise LSTM; h -> bf16 frag buffer + Os ----
#pragma unroll
        for (int bl = 0; bl < 2; bl++) {
            int b = bp * 2 + bl;
            float pi = Ds[jl * 68 + b]        + Xs[jl * 64 + b];
            float pf = Ds[(8 + jl) * 68 + b]  + Xs[(8 + jl) * 64 + b];
            float pg = Ds[(16 + jl) * 68 + b] + Xs[(16 + jl) * 64 + b];
            float po = Ds[(24 + jl) * 68 + b] + Xs[(24 + jl) * 64 + b];
            float gi = 1.f / (1.f + expf(-pi));
            float gf = 1.f / (1.f + expf(-pf));
            float gg2 = tanhf(pg);
            float go = 1.f / (1.f + expf(-po));
            float c = gf * cst[bl] + gi * gg2;
            cst[bl] = c;
            float h = go * tanhf(c);
            char* fp = (char*)(hfout + ((kgp * 8 + (b >> 3)) * 32 + (b & 7) * 4 + tgp)) + bsub;
            *(__nv_bfloat16*)fp = __float2bfloat16_rn(h);
            Os[jl * 64 + b] = h;
        }
        __threadfence();
        __syncthreads();

        // ---- arrive ----
        if (tid == 0) {
            unsigned arrived = atomicAdd(&g_bar_count, 1u);
            if (arrived == NBLK - 1) {
                *(volatile unsigned*)&g_bar_count = 0u;
                __threadfence();
                *(volatile unsigned*)&g_bar_epoch = e0 + (unsigned)t + 1u;
            }
        }

        // ---- overlapped tail: seq store + next Xs stage ----
        if (store_seq) {
#pragma unroll
            for (int i = 0; i < 2; i++) {
                int idx = tid + i * 256;
                int jj = idx & 7;
                int b = idx >> 3;
                hs_out[((long)b * Tt + t) * Hh + j0 + jj] = Os[jj * 64 + b];
            }
        } else if (t == Tt - 1) {
#pragma unroll
            for (int i = 0; i < 2; i++) {
                int idx = tid + i * 256;
                int jj = idx & 7;
                int b = idx >> 3;
                hs_out[(long)b * Hh + j0 + jj] = Os[jj * 64 + b];
            }
        }
        if (t + 1 < Tt) {
#pragma unroll
            for (int i = 0; i < 8; i++) {
                int idx = tid + i * 256;
                int jj = idx & 7;
                int gate = (idx >> 3) & 3;
                int b = idx >> 5;
                Xs[(gate * 8 + jj) * 64 + b] =
                    xg[((long)b * Tt + (t + 1)) * G4 + gate * Hh + j0 + jj];
            }
        }

        // ---- wait ----
        if (tid == 0) {
            while (*(volatile unsigned*)&g_bar_epoch < e0 + (unsigned)t + 1u) { }
        }
        __syncthreads();

        const uint2* tmp = hfin; hfin = hfout; hfout = (uint2*)tmp;
    }
}

// ---------------------------------------------------------------------------
// kernel_launch: 7 graph nodes
// ---------------------------------------------------------------------------
extern "C" void kernel_launch(void* const* d_in, const int* in_sizes, int n_in,
                              void* d_out, int out_size) {
    const float* x     = (const float*)d_in[0];
    const float* W_ih0 = (const float*)d_in[1];
    const float* W_hh0 = (const float*)d_in[2];
    const float* b_ih0 = (const float*)d_in[3];
    const float* b_hh0 = (const float*)d_in[4];
    const float* W_ih1 = (const float*)d_in[5];
    const float* W_hh1 = (const float*)d_in[6];
    const float* b_ih1 = (const float*)d_in[7];
    const float* b_hh1 = (const float*)d_in[8];
    const float* fc_w  = (const float*)d_in[9];
    const float* fc_b  = (const float*)d_in[10];
    float* out = (float*)d_out;

    float *xg, *hs, *hlast;
    uint2 *hfA, *hfB;
    cudaGetSymbolAddress((void**)&xg, g_xg);
    cudaGetSymbolAddress((void**)&hs, g_hs);
    cudaGetSymbolAddress((void**)&hfA, g_hfA);
    cudaGetSymbolAddress((void**)&hfB, g_hfB);
    cudaGetSymbolAddress((void**)&hlast, g_hlast);

    const int fragN = 64 * 8 * 32 * 2;                  // uint32 per frag buffer
    const int SMEM_PERSIST = SMP_TOT * sizeof(float);   // 88,576 B
    const int SMEM_GEMM = 4 * 4608 * sizeof(float);     // 73,728 B

    static int smem_set = 0;
    if (!smem_set) {
        cudaFuncSetAttribute(lstm_persist_bf16_kernel,
                             cudaFuncAttributeMaxDynamicSharedMemorySize,
                             SMEM_PERSIST);
        cudaFuncSetAttribute(tf32_gemm_async_kernel,
                             cudaFuncAttributeMaxDynamicSharedMemorySize,
                             SMEM_GEMM);
        smem_set = 1;
    }

    // ---------------- Layer 0 ----------------
    zero2_kernel<<<(fragN + 255) / 256, 256>>>((float*)hfA, (float*)hfB, fragN);

    {   // xg0 = x @ W_ih0^T + b_ih0 + b_hh0
        dim3 grid(G4 / 128, (Bb * Tt) / 128);
        tf32_gemm_async_kernel<<<grid, 256, SMEM_GEMM>>>(x, W_ih0, b_ih0, b_hh0, xg,
                                                         Bb * Tt, G4, IN_DIM);
    }

    lstm_persist_bf16_kernel<<<NBLK, 256, SMEM_PERSIST>>>(
        xg, W_hh0, hfA, hfB, hs, 1);

    // ---------------- Layer 1 ----------------
    zero2_kernel<<<(fragN + 255) / 256, 256>>>((float*)hfA, (float*)hfB, fragN);

    {   // xg1 = hs0 @ W_ih1^T + b_ih1 + b_hh1
        dim3 grid(G4 / 128, (Bb * Tt) / 128);
        tf32_gemm_async_kernel<<<grid, 256, SMEM_GEMM>>>(hs, W_ih1, b_ih1, b_hh1, xg,
                                                         Bb * Tt, G4, Hh);
    }

    lstm_persist_bf16_kernel<<<NBLK, 256, SMEM_PERSIST>>>(
        xg, W_hh1, hfA, hfB, hlast, 0);

    // ---------------- FC ----------------
    {
        dim3 grid((NCLS + 63) / 64, (Bb + 127) / 128);
        sgemm_bias_kernel<<<grid, 256>>>(hlast, fc_w, fc_b, nullptr, out,
                                         Bb, NCLS, Hh);
    }
}

// round 15
// speedup vs baseline: 6.0858x; 1.1062x over previous
#include <cuda_runtime.h>
#include <cuda_bf16.h>
#include <math.h>
#include <stdint.h>

// Problem dims (fixed)
#define Bb 64
#define Tt 512
#define IN_DIM 512
#define Hh 1024
#define G4 4096
#define NCLS 1000
#define NBLK 128   // persistent grid; single wave on 148 SMs

// Scratch (device globals; no allocation allowed)
__device__ float  g_xg[(size_t)Bb * Tt * G4];    // layer-0 pre-activations
// h in bf16 B-fragment layout: uint2 per (kg, nt, lane)
__device__ uint2  g_hf0A[64 * 8 * 32];    // layer-0 h_hi ping
__device__ uint2  g_hf0B[64 * 8 * 32];    // layer-0 h_hi pong
__device__ uint2  g_hf0loA[64 * 8 * 32];  // layer-0 h_lo ping
__device__ uint2  g_hf0loB[64 * 8 * 32];  // layer-0 h_lo pong
__device__ uint2  g_hf1A[64 * 8 * 32];    // layer-1 h ping
__device__ uint2  g_hf1B[64 * 8 * 32];    // layer-1 h pong
// W_hh1 bf16 A-fragments, block-private: [bid][kg*2+mt][lane]
__device__ uint4  g_Wf1hh[NBLK * 64 * 2 * 32];   // 8 MB, L2-resident
__device__ float  g_hlast[Bb * Hh];

__device__ unsigned g_bar_count = 0;
__device__ unsigned g_bar_epoch = 0;

// ---------------------------------------------------------------------------
__global__ void zero6_kernel(float* a, float* b, float* c,
                             float* d, float* e, float* f, int n) {
    int i = blockIdx.x * blockDim.x + threadIdx.x;
    if (i < n) { a[i] = 0.f; b[i] = 0.f; c[i] = 0.f;
                 d[i] = 0.f; e[i] = 0.f; f[i] = 0.f; }
}

// ---------------------------------------------------------------------------
// helpers
// ---------------------------------------------------------------------------
__device__ __forceinline__ uint32_t f2tf32u(float x) {
    uint32_t u;
    asm("cvt.rna.tf32.f32 %0, %1;" : "=r"(u) : "f"(x));
    return u;
}

// low element = first arg
__device__ __forceinline__ uint32_t pack_bf16x2(float lo, float hi) {
    uint32_t r;
    asm("cvt.rn.bf16x2.f32 %0, %1, %2;" : "=r"(r) : "f"(hi), "f"(lo));
    return r;
}

// split a,b (fp32) into bf16 hi pair + bf16 lo pair (a in low half)
__device__ __forceinline__ void split_bf16x2(float a, float b,
                                             uint32_t& hi, uint32_t& lo) {
    __nv_bfloat16 ah = __float2bfloat16_rn(a);
    __nv_bfloat16 bh = __float2bfloat16_rn(b);
    float alo = a - __bfloat162float(ah);
    float blo = b - __bfloat162float(bh);
    hi = ((uint32_t)__bfloat16_as_ushort(bh) << 16) | (uint32_t)__bfloat16_as_ushort(ah);
    lo = pack_bf16x2(alo, blo);
}

__device__ __forceinline__ void mma_tf32(float c[4],
                                         uint32_t a0, uint32_t a1, uint32_t a2, uint32_t a3,
                                         uint32_t b0, uint32_t b1) {
    asm volatile(
        "mma.sync.aligned.m16n8k8.row.col.f32.tf32.tf32.f32 "
        "{%0,%1,%2,%3}, {%4,%5,%6,%7}, {%8,%9}, {%0,%1,%2,%3};"
        : "+f"(c[0]), "+f"(c[1]), "+f"(c[2]), "+f"(c[3])
        : "r"(a0), "r"(a1), "r"(a2), "r"(a3), "r"(b0), "r"(b1));
}

__device__ __forceinline__ void mma_bf16(float c[4],
                                         uint32_t a0, uint32_t a1, uint32_t a2, uint32_t a3,
                                         uint32_t b0, uint32_t b1) {
    asm volatile(
        "mma.sync.aligned.m16n8k16.row.col.f32.bf16.bf16.f32 "
        "{%0,%1,%2,%3}, {%4,%5,%6,%7}, {%8,%9}, {%0,%1,%2,%3};"
        : "+f"(c[0]), "+f"(c[1]), "+f"(c[2]), "+f"(c[3])
        : "r"(a0), "r"(a1), "r"(a2), "r"(a3), "r"(b0), "r"(b1));
}

__device__ __forceinline__ uint32_t smem_u32(const void* p) {
    uint32_t a;
    asm("{ .reg .u64 t; cvta.to.shared.u64 t, %1; cvt.u32.u64 %0, t; }"
        : "=r"(a) : "l"(p));
    return a;
}

__device__ __forceinline__ void cp16(uint32_t dst, const void* src) {
    asm volatile("cp.async.cg.shared.global [%0], [%1], 16;" :: "r"(dst), "l"(src));
}

// ---------------------------------------------------------------------------
// tf32 GEMM (proven): C = A @ W^T + bias1 + bias2, cp.async double-buffered.
// ---------------------------------------------------------------------------
__global__ __launch_bounds__(256, 2)
void tf32_gemm_async_kernel(const float* __restrict__ A,
                            const float* __restrict__ W,
                            const float* __restrict__ bias1,
                            const float* __restrict__ bias2,
                            float* __restrict__ C,
                            int M, int N, int K) {
    extern __shared__ float gsm[];
    float* Abuf[2] = { gsm,            gsm + 9216  };
    float* Wbuf[2] = { gsm + 4608,     gsm + 13824 };

    const int tid  = threadIdx.x;
    const int lane = tid & 31;
    const int warp = tid >> 5;
    const int wm = warp >> 2;
    const int wn = warp & 3;
    const int g  = lane >> 2;
    const int tg = lane & 3;

    const long m0 = (long)blockIdx.y * 128;
    const long n0 = (long)blockIdx.x * 128;
    const int ntiles = K >> 5;

    float acc[4][4][4];
#pragma unroll
    for (int i = 0; i < 4; i++)
#pragma unroll
        for (int j = 0; j < 4; j++)
#pragma unroll
            for (int r = 0; r < 4; r++) acc[i][j][r] = 0.f;

    auto stage = [&](int tile, int buf) {
        const long k0 = (long)tile * 32;
        uint32_t sa = smem_u32(Abuf[buf]);
        uint32_t sw = smem_u32(Wbuf[buf]);
#pragma unroll
        for (int i = 0; i < 4; i++) {
            int idx = tid + i * 256;
            int r = idx >> 3;
            int c4 = (idx & 7) * 4;
            uint32_t off = (uint32_t)(r * 36 + c4) * 4u;
            cp16(sa + off, &A[(m0 + r) * K + k0 + c4]);
            cp16(sw + off, &W[(n0 + r) * K + k0 + c4]);
        }
        asm volatile("cp.async.commit_group;");
    };

    stage(0, 0);
    stage(1, 1);

    for (int t = 0; t < ntiles; t++) {
        const int buf = t & 1;
        asm volatile("cp.async.wait_group 1;");
        __syncthreads();

        const float* As = Abuf[buf];
        const float* Ws = Wbuf[buf];
#pragma unroll
        for (int k8 = 0; k8 < 4; k8++) {
            const int kb = k8 * 8;
            uint32_t af[4][4];
#pragma unroll
            for (int mt = 0; mt < 4; mt++) {
                const float* ab = &As[(wm * 64 + mt * 16 + g) * 36 + kb + tg];
                af[mt][0] = f2tf32u(ab[0]);
                af[mt][2] = f2tf32u(ab[4]);
                af[mt][1] = f2tf32u(ab[8 * 36]);
                af[mt][3] = f2tf32u(ab[8 * 36 + 4]);
            }
            uint32_t bf[4][2];
#pragma unroll
            for (int nt = 0; nt < 4; nt++) {
                const float* bb = &Ws[(wn * 32 + nt * 8 + g) * 36 + kb + tg];
                bf[nt][0] = f2tf32u(bb[0]);
                bf[nt][1] = f2tf32u(bb[4]);
            }
#pragma unroll
            for (int mt = 0; mt < 4; mt++)
#pragma unroll
                for (int nt = 0; nt < 4; nt++)
                    mma_tf32(acc[mt][nt], af[mt][0], af[mt][1], af[mt][2], af[mt][3],
                             bf[nt][0], bf[nt][1]);
        }
        __syncthreads();
        if (t + 2 < ntiles) stage(t + 2, buf);
    }

#pragma unroll
    for (int mt = 0; mt < 4; mt++) {
#pragma unroll
        for (int nt = 0; nt < 4; nt++) {
            long row0 = m0 + wm * 64 + mt * 16 + g;
            long col  = n0 + wn * 32 + nt * 8 + tg * 2;
            float bsum0 = (bias1 ? bias1[col]     : 0.f) + (bias2 ? bias2[col]     : 0.f);
            float bsum1 = (bias1 ? bias1[col + 1] : 0.f) + (bias2 ? bias2[col + 1] : 0.f);
            float2 v0 = make_float2(acc[mt][nt][0] + bsum0, acc[mt][nt][1] + bsum1);
            float2 v1 = make_float2(acc[mt][nt][2] + bsum0, acc[mt][nt][3] + bsum1);
            *(float2*)&C[row0 * N + col] = v0;
            *(float2*)&C[(row0 + 8) * N + col] = v1;
        }
    }
}

// ---------------------------------------------------------------------------
// fp32 SGEMM (FC only)
// ---------------------------------------------------------------------------
__global__ void sgemm_bias_kernel(const float* __restrict__ A,
                                  const float* __restrict__ W,
                                  const float* __restrict__ bias1,
                                  const float* __restrict__ bias2,
                                  float* __restrict__ C,
                                  int M, int N, int K) {
    __shared__ __align__(16) float As[16 * 132];
    __shared__ __align__(16) float Ws[16 * 68];
    const int m0 = blockIdx.y * 128;
    const int n0 = blockIdx.x * 64;
    const int tid = threadIdx.x;
    const int tx = tid & 15;
    const int ty = tid >> 4;
    float acc[8][4] = {};

    for (int k0 = 0; k0 < K; k0 += 16) {
#pragma unroll
        for (int i = 0; i < 8; i++) {
            int idx = tid + i * 256;
            int k = idx & 15;
            int r = idx >> 4;
            As[k * 132 + r] = (m0 + r < M) ? A[(long)(m0 + r) * K + k0 + k] : 0.f;
        }
#pragma unroll
        for (int i = 0; i < 4; i++) {
            int idx = tid + i * 256;
            int k = idx & 15;
            int r = idx >> 4;
            Ws[k * 68 + r] = (n0 + r < N) ? W[(long)(n0 + r) * K + k0 + k] : 0.f;
        }
        __syncthreads();
#pragma unroll
        for (int kk = 0; kk < 16; kk++) {
            float4 b = *(const float4*)&Ws[kk * 68 + tx * 4];
            float4 a0 = *(const float4*)&As[kk * 132 + ty * 8];
            float4 a1 = *(const float4*)&As[kk * 132 + ty * 8 + 4];
            acc[0][0] += a0.x * b.x; acc[0][1] += a0.x * b.y; acc[0][2] += a0.x * b.z; acc[0][3] += a0.x * b.w;
            acc[1][0] += a0.y * b.x; acc[1][1] += a0.y * b.y; acc[1][2] += a0.y * b.z; acc[1][3] += a0.y * b.w;
            acc[2][0] += a0.z * b.x; acc[2][1] += a0.z * b.y; acc[2][2] += a0.z * b.z; acc[2][3] += a0.z * b.w;
            acc[3][0] += a0.w * b.x; acc[3][1] += a0.w * b.y; acc[3][2] += a0.w * b.z; acc[3][3] += a0.w * b.w;
            acc[4][0] += a1.x * b.x; acc[4][1] += a1.x * b.y; acc[4][2] += a1.x * b.z; acc[4][3] += a1.x * b.w;
            acc[5][0] += a1.y * b.x; acc[5][1] += a1.y * b.y; acc[5][2] += a1.y * b.z; acc[5][3] += a1.y * b.w;
            acc[6][0] += a1.z * b.x; acc[6][1] += a1.z * b.y; acc[6][2] += a1.z * b.z; acc[6][3] += a1.z * b.w;
            acc[7][0] += a1.w * b.x; acc[7][1] += a1.w * b.y; acc[7][2] += a1.w * b.z; acc[7][3] += a1.w * b.w;
        }
        __syncthreads();
    }

#pragma unroll
    for (int i = 0; i < 8; i++) {
        int m = m0 + ty * 8 + i;
        if (m >= M) continue;
#pragma unroll
        for (int j = 0; j < 4; j++) {
            int n = n0 + tx * 4 + j;
            if (n >= N) continue;
            float bsum = (bias1 ? bias1[n] : 0.f) + (bias2 ? bias2[n] : 0.f);
            C[(long)m * N + n] = acc[i][j] + bsum;
        }
    }
}

// ---------------------------------------------------------------------------
// Fused 2-layer persistent LSTM (wavefront), precision-hardened:
//   L0: K=1024, W_hh0 bf16 frags in REGISTERS (proven).
//   L1: ih-path split-bf16 3-product (W_ih1 = hi+lo in smem; h0 = hi+lo frag
//       rings) -> ~17-bit effective precision; hh-path single bf16 with W_hh1
//       frags in a block-private GLOBAL array (L2-resident).
// Every warp k-splits: warp w owns kg in [8w, 8w+8) for every pass.
// smem (floats): WihHi 16384 | WihLo 16384 | Ps 17408 | Ds 2176 | Xs 2048 | bs1 32
// ---------------------------------------------------------------------------
#define SMF_WHI 0
#define SMF_WLO 16384
#define SMF_PS  32768
#define SMF_DS  (SMF_PS + 17408)
#define SMF_XS  (SMF_DS + 2176)
#define SMF_BS  (SMF_XS + 2048)
#define SMF_TOT (SMF_BS + 32)     // 54432 floats = 217,728 B

__global__ __launch_bounds__(256, 1)
void lstm_fused_kernel(const float* __restrict__ xg0,
                       const float* __restrict__ W_hh0,
                       const float* __restrict__ W_ih1,
                       const float* __restrict__ W_hh1,
                       const float* __restrict__ b_ih1,
                       const float* __restrict__ b_hh1,
                       uint2* hf0A, uint2* hf0B,
                       uint2* hf0loA, uint2* hf0loB,
                       uint2* hf1A, uint2* hf1B,
                       uint4* gWhh1,
                       float* __restrict__ hlast) {
    extern __shared__ float smem[];
    uint4* WfHi = (uint4*)(smem + SMF_WHI);
    uint4* WfLo = (uint4*)(smem + SMF_WLO);
    float* Ps  = smem + SMF_PS;
    float* Ds  = smem + SMF_DS;
    float* Xs  = smem + SMF_XS;
    float* bs1 = smem + SMF_BS;

    const int tid  = threadIdx.x;      // 256
    const int lane = tid & 31;
    const int w    = tid >> 5;         // warp 0..7
    const int g    = lane >> 2;
    const int tg   = lane & 3;
    const int bid  = blockIdx.x;
    const int j0   = bid * 8;
    const int bp   = lane;
    const int jl   = w;

    __shared__ unsigned s_e0;
    if (tid == 0) s_e0 = *(volatile unsigned*)&g_bar_epoch;
    __syncthreads();
    const unsigned e0 = s_e0;

    // ---- one-time: L0 W_hh0 fragments -> registers (proven layout) ----
    uint4 af0[8], af1[8];
#pragma unroll
    for (int kgl = 0; kgl < 8; kgl++) {
        int kg = w * 8 + kgl;
        int k0 = kg * 16 + 2 * tg;
        int kh = k0 + 8;
        int r;
        long rowA, rowB;
        r = g;       rowA = (long)((r >> 3) * Hh + j0 + (r & 7)) * Hh;
        r = g + 8;   rowB = (long)((r >> 3) * Hh + j0 + (r & 7)) * Hh;
        af0[kgl].x = pack_bf16x2(W_hh0[rowA + k0], W_hh0[rowA + k0 + 1]);
        af0[kgl].y = pack_bf16x2(W_hh0[rowB + k0], W_hh0[rowB + k0 + 1]);
        af0[kgl].z = pack_bf16x2(W_hh0[rowA + kh], W_hh0[rowA + kh + 1]);
        af0[kgl].w = pack_bf16x2(W_hh0[rowB + kh], W_hh0[rowB + kh + 1]);
        r = 16 + g;  rowA = (long)((r >> 3) * Hh + j0 + (r & 7)) * Hh;
        r = 24 + g;  rowB = (long)((r >> 3) * Hh + j0 + (r & 7)) * Hh;
        af1[kgl].x = pack_bf16x2(W_hh0[rowA + k0], W_hh0[rowA + k0 + 1]);
        af1[kgl].y = pack_bf16x2(W_hh0[rowB + k0], W_hh0[rowB + k0 + 1]);
        af1[kgl].z = pack_bf16x2(W_hh0[rowA + kh], W_hh0[rowA + kh + 1]);
        af1[kgl].w = pack_bf16x2(W_hh0[rowB + kh], W_hh0[rowB + kh + 1]);
    }

    // ---- one-time: W_ih1 split (hi/lo) fragments -> smem (K=1024) ----
    // index: (kg*2 + mt)*32 + lane, kg in [0,64)
    for (int i = tid; i < 4096; i += 256) {
        int l   = i & 31;
        int grp = i >> 5;             // kg*2 + mt
        int mt  = grp & 1;
        int kg  = grp >> 1;
        int gg = l >> 2, tt = l & 3;
        int kl = kg * 16 + 2 * tt;
        int kh = kl + 8;
        int rA = mt * 16 + gg;
        int rB = rA + 8;
        long rowA = (long)((rA >> 3) * Hh + j0 + (rA & 7)) * Hh;
        long rowB = (long)((rB >> 3) * Hh + j0 + (rB & 7)) * Hh;
        uint4 vh, vl;
        split_bf16x2(W_ih1[rowA + kl], W_ih1[rowA + kl + 1], vh.x, vl.x);
        split_bf16x2(W_ih1[rowB + kl], W_ih1[rowB + kl + 1], vh.y, vl.y);
        split_bf16x2(W_ih1[rowA + kh], W_ih1[rowA + kh + 1], vh.z, vl.z);
        split_bf16x2(W_ih1[rowB + kh], W_ih1[rowB + kh + 1], vh.w, vl.w);
        WfHi[i] = vh;
        WfLo[i] = vl;
    }

    // ---- one-time: W_hh1 bf16 fragments -> block-private GLOBAL ----
    uint4* myWhh = gWhh1 + (long)bid * 4096;
    for (int i = tid; i < 4096; i += 256) {
        int l   = i & 31;
        int grp = i >> 5;
        int mt  = grp & 1;
        int kg  = grp >> 1;
        int gg = l >> 2, tt = l & 3;
        int kl = kg * 16 + 2 * tt;
        int kh = kl + 8;
        int rA = mt * 16 + gg;
        int rB = rA + 8;
        long rowA = (long)((rA >> 3) * Hh + j0 + (rA & 7)) * Hh;
        long rowB = (long)((rB >> 3) * Hh + j0 + (rB & 7)) * Hh;
        uint4 v;
        v.x = pack_bf16x2(W_hh1[rowA + kl], W_hh1[rowA + kl + 1]);
        v.y = pack_bf16x2(W_hh1[rowB + kl], W_hh1[rowB + kl + 1]);
        v.z = pack_bf16x2(W_hh1[rowA + kh], W_hh1[rowA + kh + 1]);
        v.w = pack_bf16x2(W_hh1[rowB + kh], W_hh1[rowB + kh + 1]);
        myWhh[i] = v;
    }

    // ---- one-time: L1 bias sums ----
    if (tid < 32) {
        int gate = tid >> 3, jj = tid & 7;
        bs1[tid] = b_ih1[gate * Hh + j0 + jj] + b_hh1[gate * Hh + j0 + jj];
    }

    // producer frag-write geometry (proven)
    const int jj16 = ((bid & 1) << 3) + jl;
    const int tgp  = (jj16 & 7) >> 1;
    const int bsub = ((jj16 >= 8) ? 4 : 0) + (jj16 & 1) * 2;
    const int kgp  = bid >> 1;

    float cst0[2] = {0.f, 0.f};
    float cst1[2] = {0.f, 0.f};
    __syncthreads();   // also makes myWhh global writes visible block-wide

    // stage Xs for s=0
#pragma unroll
    for (int i = 0; i < 8; i++) {
        int idx = tid + i * 256;
        int jj = idx & 7;
        int gate = (idx >> 3) & 3;
        int b = idx >> 5;
        Xs[(gate * 8 + jj) * 64 + b] =
            xg0[((long)b * Tt + 0) * G4 + gate * Hh + j0 + jj];
    }

    for (int s = 0; s <= Tt; s++) {
        const uint2* hf0prev   = (s & 1) ? hf0A   : hf0B;
        uint2*       hf0out    = (s & 1) ? hf0B   : hf0A;
        const uint2* hf0loprev = (s & 1) ? hf0loA : hf0loB;
        uint2*       hf0loout  = (s & 1) ? hf0loB : hf0loA;
        const uint2* hf1prev   = (s & 1) ? hf1A   : hf1B;
        uint2*       hf1out    = (s & 1) ? hf1B   : hf1A;

        // ================= Layer 0, step s =================
        if (s < Tt) {
            float acc0[8][4], acc1[8][4];
#pragma unroll
            for (int nt = 0; nt < 8; nt++)
#pragma unroll
                for (int r = 0; r < 4; r++) { acc0[nt][r] = 0.f; acc1[nt][r] = 0.f; }

            const uint2* hb = hf0prev + (w * 64) * 32 + lane;
            uint2 Bq[8];
#pragma unroll
            for (int p = 0; p < 8; p++) Bq[p] = __ldcg(hb + p * 32);
#pragma unroll
            for (int i = 0; i < 64; i++) {
                uint2 B = Bq[i & 7];
                if (i + 8 < 64) Bq[i & 7] = __ldcg(hb + (i + 8) * 32);
                const int kgl = i >> 3;
                const int nt  = i & 7;
                mma_bf16(acc0[nt], af0[kgl].x, af0[kgl].y, af0[kgl].z, af0[kgl].w, B.x, B.y);
                mma_bf16(acc1[nt], af1[kgl].x, af1[kgl].y, af1[kgl].z, af1[kgl].w, B.x, B.y);
            }
            float* myPs = Ps + w * 2176;
#pragma unroll
            for (int nt = 0; nt < 8; nt++) {
                int c0 = nt * 8 + tg * 2;
                *(float2*)&myPs[g * 68 + c0]        = make_float2(acc0[nt][0], acc0[nt][1]);
                *(float2*)&myPs[(g + 8) * 68 + c0]  = make_float2(acc0[nt][2], acc0[nt][3]);
                *(float2*)&myPs[(16 + g) * 68 + c0] = make_float2(acc1[nt][0], acc1[nt][1]);
                *(float2*)&myPs[(24 + g) * 68 + c0] = make_float2(acc1[nt][2], acc1[nt][3]);
            }
        }
        __syncthreads();
        if (s < Tt) {
            int row  = tid >> 3;
            int col0 = (tid & 7) * 8;
            float4 s0 = make_float4(0.f, 0.f, 0.f, 0.f);
            float4 s1 = make_float4(0.f, 0.f, 0.f, 0.f);
#pragma unroll
            for (int ww = 0; ww < 8; ww++) {
                const float* p = Ps + ww * 2176 + row * 68 + col0;
                float4 a = *(const float4*)p;
                float4 b = *(const float4*)(p + 4);
                s0.x += a.x; s0.y += a.y; s0.z += a.z; s0.w += a.w;
                s1.x += b.x; s1.y += b.y; s1.z += b.z; s1.w += b.w;
            }
            *(float4*)&Ds[row * 68 + col0]     = s0;
            *(float4*)&Ds[row * 68 + col0 + 4] = s1;
        }
        __syncthreads();
        if (s < Tt) {
#pragma unroll
            for (int bl = 0; bl < 2; bl++) {
                int b = bp * 2 + bl;
                float pi = Ds[jl * 68 + b]        + Xs[jl * 64 + b];
                float pf = Ds[(8 + jl) * 68 + b]  + Xs[(8 + jl) * 64 + b];
                float pg = Ds[(16 + jl) * 68 + b] + Xs[(16 + jl) * 64 + b];
                float po = Ds[(24 + jl) * 68 + b] + Xs[(24 + jl) * 64 + b];
                float gi = 1.f / (1.f + expf(-pi));
                float gf = 1.f / (1.f + expf(-pf));
                float gg2 = tanhf(pg);
                float go = 1.f / (1.f + expf(-po));
                float c = gf * cst0[bl] + gi * gg2;
                cst0[bl] = c;
                float h = go * tanhf(c);
                // write h_hi and h_lo frags
                long fo = (kgp * 8 + (b >> 3)) * 32 + (b & 7) * 4 + tgp;
                __nv_bfloat16 hhi = __float2bfloat16_rn(h);
                float hlo = h - __bfloat162float(hhi);
                *(__nv_bfloat16*)((char*)(hf0out + fo) + bsub)   = hhi;
                *(__nv_bfloat16*)((char*)(hf0loout + fo) + bsub) = __float2bfloat16_rn(hlo);
            }
        }

        // ================= Layer 1, step s-1 =================
        if (s >= 1) {
            float acc0[8][4], acc1[8][4];
#pragma unroll
            for (int nt = 0; nt < 8; nt++)
#pragma unroll
                for (int r = 0; r < 4; r++) { acc0[nt][r] = 0.f; acc1[nt][r] = 0.f; }

            // ---- Pass 1: B = h0_hi; W = WfHi and WfLo (4 mma per frag) ----
            {
                const uint2* hb = hf0prev + (w * 64) * 32 + lane;
                uint2 Bq[8];
#pragma unroll
                for (int p = 0; p < 8; p++) Bq[p] = __ldcg(hb + p * 32);
#pragma unroll
                for (int kgl = 0; kgl < 8; kgl++) {
                    const int kg = w * 8 + kgl;
                    uint4 wh0 = WfHi[(kg * 2 + 0) * 32 + lane];
                    uint4 wh1 = WfHi[(kg * 2 + 1) * 32 + lane];
                    uint4 wl0 = WfLo[(kg * 2 + 0) * 32 + lane];
                    uint4 wl1 = WfLo[(kg * 2 + 1) * 32 + lane];
#pragma unroll
                    for (int nt = 0; nt < 8; nt++) {
                        int i = kgl * 8 + nt;
                        uint2 B = Bq[i & 7];
                        if (i + 8 < 64) Bq[i & 7] = __ldcg(hb + (i + 8) * 32);
                        mma_bf16(acc0[nt], wh0.x, wh0.y, wh0.z, wh0.w, B.x, B.y);
                        mma_bf16(acc1[nt], wh1.x, wh1.y, wh1.z, wh1.w, B.x, B.y);
                        mma_bf16(acc0[nt], wl0.x, wl0.y, wl0.z, wl0.w, B.x, B.y);
                        mma_bf16(acc1[nt], wl1.x, wl1.y, wl1.z, wl1.w, B.x, B.y);
                    }
                }
            }
            // ---- Pass 2: B = h0_lo; W = WfHi (2 mma per frag) ----
            {
                const uint2* hb = hf0loprev + (w * 64) * 32 + lane;
                uint2 Bq[8];
#pragma unroll
                for (int p = 0; p < 8; p++) Bq[p] = __ldcg(hb + p * 32);
#pragma unroll
                for (int kgl = 0; kgl < 8; kgl++) {
                    const int kg = w * 8 + kgl;
                    uint4 wh0 = WfHi[(kg * 2 + 0) * 32 + lane];
                    uint4 wh1 = WfHi[(kg * 2 + 1) * 32 + lane];
#pragma unroll
                    for (int nt = 0; nt < 8; nt++) {
                        int i = kgl * 8 + nt;
                        uint2 B = Bq[i & 7];
                        if (i + 8 < 64) Bq[i & 7] = __ldcg(hb + (i + 8) * 32);
                        mma_bf16(acc0[nt], wh0.x, wh0.y, wh0.z, wh0.w, B.x, B.y);
                        mma_bf16(acc1[nt], wh1.x, wh1.y, wh1.z, wh1.w, B.x, B.y);
                    }
                }
            }
            // ---- Pass 3: B = h1_prev; W = gWhh1 (block-private, L2) ----
            {
                const uint2* hb = hf1prev + (w * 64) * 32 + lane;
                uint2 Bq[8];
#pragma unroll
                for (int p = 0; p < 8; p++) Bq[p] = __ldcg(hb + p * 32);
#pragma unroll
                for (int kgl = 0; kgl < 8; kgl++) {
                    const int kg = w * 8 + kgl;
                    uint4 wh0 = __ldcg(myWhh + (kg * 2 + 0) * 32 + lane);
                    uint4 wh1 = __ldcg(myWhh + (kg * 2 + 1) * 32 + lane);
#pragma unroll
                    for (int nt = 0; nt < 8; nt++) {
                        int i = kgl * 8 + nt;
                        uint2 B = Bq[i & 7];
                        if (i + 8 < 64) Bq[i & 7] = __ldcg(hb + (i + 8) * 32);
                        mma_bf16(acc0[nt], wh0.x, wh0.y, wh0.z, wh0.w, B.x, B.y);
                        mma_bf16(acc1[nt], wh1.x, wh1.y, wh1.z, wh1.w, B.x, B.y);
                    }
                }
            }

            float* myPs = Ps + w * 2176;
#pragma unroll
            for (int nt = 0; nt < 8; nt++) {
                int c0 = nt * 8 + tg * 2;
                *(float2*)&myPs[g * 68 + c0]        = make_float2(acc0[nt][0], acc0[nt][1]);
                *(float2*)&myPs[(g + 8) * 68 + c0]  = make_float2(acc0[nt][2], acc0[nt][3]);
                *(float2*)&myPs[(16 + g) * 68 + c0] = make_float2(acc1[nt][0], acc1[nt][1]);
                *(float2*)&myPs[(24 + g) * 68 + c0] = make_float2(acc1[nt][2], acc1[nt][3]);
            }
        }
        __syncthreads();
        if (s >= 1) {
            int row  = tid >> 3;
            int col0 = (tid & 7) * 8;
            float4 s0 = make_float4(0.f, 0.f, 0.f, 0.f);
            float4 s1 = make_float4(0.f, 0.f, 0.f, 0.f);
#pragma unroll
            for (int ww = 0; ww < 8; ww++) {
                const float* p = Ps + ww * 2176 + row * 68 + col0;
                float4 a = *(const float4*)p;
                float4 b = *(const float4*)(p + 4);
                s0.x += a.x; s0.y += a.y; s0.z += a.z; s0.w += a.w;
                s1.x += b.x; s1.y += b.y; s1.z += b.z; s1.w += b.w;
            }
            *(float4*)&Ds[row * 68 + col0]     = s0;
            *(float4*)&Ds[row * 68 + col0 + 4] = s1;
        }
        __syncthreads();
        if (s >= 1) {
#pragma unroll
            for (int bl = 0; bl < 2; bl++) {
                int b = bp * 2 + bl;
                float pi = Ds[jl * 68 + b]        + bs1[jl];
                float pf = Ds[(8 + jl) * 68 + b]  + bs1[8 + jl];
                float pg = Ds[(16 + jl) * 68 + b] + bs1[16 + jl];
                float po = Ds[(24 + jl) * 68 + b] + bs1[24 + jl];
                float gi = 1.f / (1.f + expf(-pi));
                float gf = 1.f / (1.f + expf(-pf));
                float gg2 = tanhf(pg);
                float go = 1.f / (1.f + expf(-po));
                float c = gf * cst1[bl] + gi * gg2;
                cst1[bl] = c;
                float h = go * tanhf(c);
                char* fp = (char*)(hf1out + ((kgp * 8 + (b >> 3)) * 32 + (b & 7) * 4 + tgp)) + bsub;
                *(__nv_bfloat16*)fp = __float2bfloat16_rn(h);
                if (s == Tt) hlast[(long)b * Hh + j0 + jl] = h;
            }
        }

        __threadfence();
        __syncthreads();

        // ---- arrive ----
        if (tid == 0) {
            unsigned arrived = atomicAdd(&g_bar_count, 1u);
            if (arrived == NBLK - 1) {
                *(volatile unsigned*)&g_bar_count = 0u;
                __threadfence();
                *(volatile unsigned*)&g_bar_epoch = e0 + (unsigned)s + 1u;
            }
        }

        // ---- overlapped tail: stage next Xs ----
        if (s + 1 < Tt) {
#pragma unroll
            for (int i = 0; i < 8; i++) {
                int idx = tid + i * 256;
                int jj = idx & 7;
                int gate = (idx >> 3) & 3;
                int b = idx >> 5;
                Xs[(gate * 8 + jj) * 64 + b] =
                    xg0[((long)b * Tt + (s + 1)) * G4 + gate * Hh + j0 + jj];
            }
        }

        // ---- wait ----
        if (tid == 0) {
            while (*(volatile unsigned*)&g_bar_epoch < e0 + (unsigned)s + 1u) { }
        }
        __syncthreads();
    }
}

// ---------------------------------------------------------------------------
// kernel_launch: 4 graph nodes
// ---------------------------------------------------------------------------
extern "C" void kernel_launch(void* const* d_in, const int* in_sizes, int n_in,
                              void* d_out, int out_size) {
    const float* x     = (const float*)d_in[0];
    const float* W_ih0 = (const float*)d_in[1];
    const float* W_hh0 = (const float*)d_in[2];
    const float* b_ih0 = (const float*)d_in[3];
    const float* b_hh0 = (const float*)d_in[4];
    const float* W_ih1 = (const float*)d_in[5];
    const float* W_hh1 = (const float*)d_in[6];
    const float* b_ih1 = (const float*)d_in[7];
    const float* b_hh1 = (const float*)d_in[8];
    const float* fc_w  = (const float*)d_in[9];
    const float* fc_b  = (const float*)d_in[10];
    float* out = (float*)d_out;

    float *xg, *hlast;
    uint2 *hf0A, *hf0B, *hf0loA, *hf0loB, *hf1A, *hf1B;
    uint4 *gWhh1;
    cudaGetSymbolAddress((void**)&xg, g_xg);
    cudaGetSymbolAddress((void**)&hf0A, g_hf0A);
    cudaGetSymbolAddress((void**)&hf0B, g_hf0B);
    cudaGetSymbolAddress((void**)&hf0loA, g_hf0loA);
    cudaGetSymbolAddress((void**)&hf0loB, g_hf0loB);
    cudaGetSymbolAddress((void**)&hf1A, g_hf1A);
    cudaGetSymbolAddress((void**)&hf1B, g_hf1B);
    cudaGetSymbolAddress((void**)&gWhh1, g_Wf1hh);
    cudaGetSymbolAddress((void**)&hlast, g_hlast);

    const int fragN = 64 * 8 * 32 * 2;                  // uint32 per frag buffer
    const int SMEM_FUSED = SMF_TOT * sizeof(float);     // 217,728 B
    const int SMEM_GEMM  = 4 * 4608 * sizeof(float);    // 73,728 B

    static int smem_set = 0;
    if (!smem_set) {
        cudaFuncSetAttribute(lstm_fused_kernel,
                             cudaFuncAttributeMaxDynamicSharedMemorySize,
                             SMEM_FUSED);
        cudaFuncSetAttribute(tf32_gemm_async_kernel,
                             cudaFuncAttributeMaxDynamicSharedMemorySize,
                             SMEM_GEMM);
        smem_set = 1;
    }

    // zero the six h frag ring buffers
    zero6_kernel<<<(fragN + 255) / 256, 256>>>((float*)hf0A, (float*)hf0B,
                                               (float*)hf0loA, (float*)hf0loB,
                                               (float*)hf1A, (float*)hf1B, fragN);

    // xg0 = x @ W_ih0^T + b_ih0 + b_hh0   (M=32768, N=4096, K=512)
    {
        dim3 grid(G4 / 128, (Bb * Tt) / 128);
        tf32_gemm_async_kernel<<<grid, 256, SMEM_GEMM>>>(x, W_ih0, b_ih0, b_hh0, xg,
                                                         Bb * Tt, G4, IN_DIM);
    }

    // fused 2-layer recurrence (513 wavefront iterations)
    lstm_fused_kernel<<<NBLK, 256, SMEM_FUSED>>>(
        xg, W_hh0, W_ih1, W_hh1, b_ih1, b_hh1,
        hf0A, hf0B, hf0loA, hf0loB, hf1A, hf1B, gWhh1, hlast);

    // FC: out[64,1000] = hlast @ fc_w^T + fc_b
    {
        dim3 grid((NCLS + 63) / 64, (Bb + 127) / 128);
        sgemm_bias_kernel<<<grid, 256>>>(hlast, fc_w, fc_b, nullptr, out,
                                         Bb, NCLS, Hh);
    }
}

// round 16
// speedup vs baseline: 6.1857x; 1.0164x over previous
#include <cuda_runtime.h>
#include <cuda_bf16.h>
#include <math.h>
#include <stdint.h>

// Problem dims (fixed)
#define Bb 64
#define Tt 512
#define IN_DIM 512
#define Hh 1024
#define G4 4096
#define NCLS 1000
#define NBLK 128   // persistent grid; single wave on 148 SMs

// Scratch (device globals; no allocation allowed)
__device__ float  g_xg[(size_t)Bb * Tt * G4];    // layer-0 pre-activations
// h in bf16 B-fragment layout: uint2 per (kg, nt, lane)
__device__ uint2  g_hf0A[64 * 8 * 32];    // layer-0 h_hi ping
__device__ uint2  g_hf0B[64 * 8 * 32];    // layer-0 h_hi pong
__device__ uint2  g_hf0loA[64 * 8 * 32];  // layer-0 h_lo ping
__device__ uint2  g_hf0loB[64 * 8 * 32];  // layer-0 h_lo pong
__device__ uint2  g_hf1A[64 * 8 * 32];    // layer-1 h ping
__device__ uint2  g_hf1B[64 * 8 * 32];    // layer-1 h pong
// W_hh1 bf16 A-fragments, block-private: [bid][kg*2+mt][lane]
__device__ uint4  g_Wf1hh[NBLK * 64 * 2 * 32];   // 8 MB, L2-resident
__device__ float  g_hlast[Bb * Hh];

__device__ unsigned g_bar_count = 0;
__device__ unsigned g_bar_epoch = 0;

// ---------------------------------------------------------------------------
__global__ void zero6_kernel(float* a, float* b, float* c,
                             float* d, float* e, float* f, int n) {
    int i = blockIdx.x * blockDim.x + threadIdx.x;
    if (i < n) { a[i] = 0.f; b[i] = 0.f; c[i] = 0.f;
                 d[i] = 0.f; e[i] = 0.f; f[i] = 0.f; }
}

// ---------------------------------------------------------------------------
// helpers
// ---------------------------------------------------------------------------
__device__ __forceinline__ uint32_t f2tf32u(float x) {
    uint32_t u;
    asm("cvt.rna.tf32.f32 %0, %1;" : "=r"(u) : "f"(x));
    return u;
}

// low element = first arg
__device__ __forceinline__ uint32_t pack_bf16x2(float lo, float hi) {
    uint32_t r;
    asm("cvt.rn.bf16x2.f32 %0, %1, %2;" : "=r"(r) : "f"(hi), "f"(lo));
    return r;
}

// split a,b (fp32) into bf16 hi pair + bf16 lo pair (a in low half)
__device__ __forceinline__ void split_bf16x2(float a, float b,
                                             uint32_t& hi, uint32_t& lo) {
    __nv_bfloat16 ah = __float2bfloat16_rn(a);
    __nv_bfloat16 bh = __float2bfloat16_rn(b);
    float alo = a - __bfloat162float(ah);
    float blo = b - __bfloat162float(bh);
    hi = ((uint32_t)__bfloat16_as_ushort(bh) << 16) | (uint32_t)__bfloat16_as_ushort(ah);
    lo = pack_bf16x2(alo, blo);
}

__device__ __forceinline__ void mma_tf32(float c[4],
                                         uint32_t a0, uint32_t a1, uint32_t a2, uint32_t a3,
                                         uint32_t b0, uint32_t b1) {
    asm volatile(
        "mma.sync.aligned.m16n8k8.row.col.f32.tf32.tf32.f32 "
        "{%0,%1,%2,%3}, {%4,%5,%6,%7}, {%8,%9}, {%0,%1,%2,%3};"
        : "+f"(c[0]), "+f"(c[1]), "+f"(c[2]), "+f"(c[3])
        : "r"(a0), "r"(a1), "r"(a2), "r"(a3), "r"(b0), "r"(b1));
}

__device__ __forceinline__ void mma_bf16(float c[4],
                                         uint32_t a0, uint32_t a1, uint32_t a2, uint32_t a3,
                                         uint32_t b0, uint32_t b1) {
    asm volatile(
        "mma.sync.aligned.m16n8k16.row.col.f32.bf16.bf16.f32 "
        "{%0,%1,%2,%3}, {%4,%5,%6,%7}, {%8,%9}, {%0,%1,%2,%3};"
        : "+f"(c[0]), "+f"(c[1]), "+f"(c[2]), "+f"(c[3])
        : "r"(a0), "r"(a1), "r"(a2), "r"(a3), "r"(b0), "r"(b1));
}

__device__ __forceinline__ uint32_t smem_u32(const void* p) {
    uint32_t a;
    asm("{ .reg .u64 t; cvta.to.shared.u64 t, %1; cvt.u32.u64 %0, t; }"
        : "=r"(a) : "l"(p));
    return a;
}

__device__ __forceinline__ void cp16(uint32_t dst, const void* src) {
    asm volatile("cp.async.cg.shared.global [%0], [%1], 16;" :: "r"(dst), "l"(src));
}

// ---------------------------------------------------------------------------
// tf32 GEMM (proven): C = A @ W^T + bias1 + bias2, cp.async double-buffered.
// ---------------------------------------------------------------------------
__global__ __launch_bounds__(256, 2)
void tf32_gemm_async_kernel(const float* __restrict__ A,
                            const float* __restrict__ W,
                            const float* __restrict__ bias1,
                            const float* __restrict__ bias2,
                            float* __restrict__ C,
                            int M, int N, int K) {
    extern __shared__ float gsm[];
    float* Abuf[2] = { gsm,            gsm + 9216  };
    float* Wbuf[2] = { gsm + 4608,     gsm + 13824 };

    const int tid  = threadIdx.x;
    const int lane = tid & 31;
    const int warp = tid >> 5;
    const int wm = warp >> 2;
    const int wn = warp & 3;
    const int g  = lane >> 2;
    const int tg = lane & 3;

    const long m0 = (long)blockIdx.y * 128;
    const long n0 = (long)blockIdx.x * 128;
    const int ntiles = K >> 5;

    float acc[4][4][4];
#pragma unroll
    for (int i = 0; i < 4; i++)
#pragma unroll
        for (int j = 0; j < 4; j++)
#pragma unroll
            for (int r = 0; r < 4; r++) acc[i][j][r] = 0.f;

    auto stage = [&](int tile, int buf) {
        const long k0 = (long)tile * 32;
        uint32_t sa = smem_u32(Abuf[buf]);
        uint32_t sw = smem_u32(Wbuf[buf]);
#pragma unroll
        for (int i = 0; i < 4; i++) {
            int idx = tid + i * 256;
            int r = idx >> 3;
            int c4 = (idx & 7) * 4;
            uint32_t off = (uint32_t)(r * 36 + c4) * 4u;
            cp16(sa + off, &A[(m0 + r) * K + k0 + c4]);
            cp16(sw + off, &W[(n0 + r) * K + k0 + c4]);
        }
        asm volatile("cp.async.commit_group;");
    };

    stage(0, 0);
    stage(1, 1);

    for (int t = 0; t < ntiles; t++) {
        const int buf = t & 1;
        asm volatile("cp.async.wait_group 1;");
        __syncthreads();

        const float* As = Abuf[buf];
        const float* Ws = Wbuf[buf];
#pragma unroll
        for (int k8 = 0; k8 < 4; k8++) {
            const int kb = k8 * 8;
            uint32_t af[4][4];
#pragma unroll
            for (int mt = 0; mt < 4; mt++) {
                const float* ab = &As[(wm * 64 + mt * 16 + g) * 36 + kb + tg];
                af[mt][0] = f2tf32u(ab[0]);
                af[mt][2] = f2tf32u(ab[4]);
                af[mt][1] = f2tf32u(ab[8 * 36]);
                af[mt][3] = f2tf32u(ab[8 * 36 + 4]);
            }
            uint32_t bf[4][2];
#pragma unroll
            for (int nt = 0; nt < 4; nt++) {
                const float* bb = &Ws[(wn * 32 + nt * 8 + g) * 36 + kb + tg];
                bf[nt][0] = f2tf32u(bb[0]);
                bf[nt][1] = f2tf32u(bb[4]);
            }
#pragma unroll
            for (int mt = 0; mt < 4; mt++)
#pragma unroll
                for (int nt = 0; nt < 4; nt++)
                    mma_tf32(acc[mt][nt], af[mt][0], af[mt][1], af[mt][2], af[mt][3],
                             bf[nt][0], bf[nt][1]);
        }
        __syncthreads();
        if (t + 2 < ntiles) stage(t + 2, buf);
    }

#pragma unroll
    for (int mt = 0; mt < 4; mt++) {
#pragma unroll
        for (int nt = 0; nt < 4; nt++) {
            long row0 = m0 + wm * 64 + mt * 16 + g;
            long col  = n0 + wn * 32 + nt * 8 + tg * 2;
            float bsum0 = (bias1 ? bias1[col]     : 0.f) + (bias2 ? bias2[col]     : 0.f);
            float bsum1 = (bias1 ? bias1[col + 1] : 0.f) + (bias2 ? bias2[col + 1] : 0.f);
            float2 v0 = make_float2(acc[mt][nt][0] + bsum0, acc[mt][nt][1] + bsum1);
            float2 v1 = make_float2(acc[mt][nt][2] + bsum0, acc[mt][nt][3] + bsum1);
            *(float2*)&C[row0 * N + col] = v0;
            *(float2*)&C[(row0 + 8) * N + col] = v1;
        }
    }
}

// ---------------------------------------------------------------------------
// fp32 SGEMM (FC only)
// ---------------------------------------------------------------------------
__global__ void sgemm_bias_kernel(const float* __restrict__ A,
                                  const float* __restrict__ W,
                                  const float* __restrict__ bias1,
                                  const float* __restrict__ bias2,
                                  float* __restrict__ C,
                                  int M, int N, int K) {
    __shared__ __align__(16) float As[16 * 132];
    __shared__ __align__(16) float Ws[16 * 68];
    const int m0 = blockIdx.y * 128;
    const int n0 = blockIdx.x * 64;
    const int tid = threadIdx.x;
    const int tx = tid & 15;
    const int ty = tid >> 4;
    float acc[8][4] = {};

    for (int k0 = 0; k0 < K; k0 += 16) {
#pragma unroll
        for (int i = 0; i < 8; i++) {
            int idx = tid + i * 256;
            int k = idx & 15;
            int r = idx >> 4;
            As[k * 132 + r] = (m0 + r < M) ? A[(long)(m0 + r) * K + k0 + k] : 0.f;
        }
#pragma unroll
        for (int i = 0; i < 4; i++) {
            int idx = tid + i * 256;
            int k = idx & 15;
            int r = idx >> 4;
            Ws[k * 68 + r] = (n0 + r < N) ? W[(long)(n0 + r) * K + k0 + k] : 0.f;
        }
        __syncthreads();
#pragma unroll
        for (int kk = 0; kk < 16; kk++) {
            float4 b = *(const float4*)&Ws[kk * 68 + tx * 4];
            float4 a0 = *(const float4*)&As[kk * 132 + ty * 8];
            float4 a1 = *(const float4*)&As[kk * 132 + ty * 8 + 4];
            acc[0][0] += a0.x * b.x; acc[0][1] += a0.x * b.y; acc[0][2] += a0.x * b.z; acc[0][3] += a0.x * b.w;
            acc[1][0] += a0.y * b.x; acc[1][1] += a0.y * b.y; acc[1][2] += a0.y * b.z; acc[1][3] += a0.y * b.w;
            acc[2][0] += a0.z * b.x; acc[2][1] += a0.z * b.y; acc[2][2] += a0.z * b.z; acc[2][3] += a0.z * b.w;
            acc[3][0] += a0.w * b.x; acc[3][1] += a0.w * b.y; acc[3][2] += a0.w * b.z; acc[3][3] += a0.w * b.w;
            acc[4][0] += a1.x * b.x; acc[4][1] += a1.x * b.y; acc[4][2] += a1.x * b.z; acc[4][3] += a1.x * b.w;
            acc[5][0] += a1.y * b.x; acc[5][1] += a1.y * b.y; acc[5][2] += a1.y * b.z; acc[5][3] += a1.y * b.w;
            acc[6][0] += a1.z * b.x; acc[6][1] += a1.z * b.y; acc[6][2] += a1.z * b.z; acc[6][3] += a1.z * b.w;
            acc[7][0] += a1.w * b.x; acc[7][1] += a1.w * b.y; acc[7][2] += a1.w * b.z; acc[7][3] += a1.w * b.w;
        }
        __syncthreads();
    }

#pragma unroll
    for (int i = 0; i < 8; i++) {
        int m = m0 + ty * 8 + i;
        if (m >= M) continue;
#pragma unroll
        for (int j = 0; j < 4; j++) {
            int n = n0 + tx * 4 + j;
            if (n >= N) continue;
            float bsum = (bias1 ? bias1[n] : 0.f) + (bias2 ? bias2[n] : 0.f);
            C[(long)m * N + n] = acc[i][j] + bsum;
        }
    }
}

// ---------------------------------------------------------------------------
// Fused 2-layer persistent LSTM (wavefront), v2:
// MERGED B-stream: L0's h0_hi reads and L1's ih-hi pass share one load loop
// (6 mma per fragment: af0/af1 for L0; WfHi/WfLo x2 for L1-ih).
// Then pass2 (h0_lo x WfHi) and pass3 (h1 x gWhh1) continue L1 accumulation.
// Epilogues guarded by s-range; out-of-range compute reads valid buffers and
// is discarded. Arithmetic order per accumulator identical to R15.
// smem (floats): WihHi 16384 | WihLo 16384 | Ps 17408 | Ds 2176 | Xs 2048 | bs1 32
// ---------------------------------------------------------------------------
#define SMF_WHI 0
#define SMF_WLO 16384
#define SMF_PS  32768
#define SMF_DS  (SMF_PS + 17408)
#define SMF_XS  (SMF_DS + 2176)
#define SMF_BS  (SMF_XS + 2048)
#define SMF_TOT (SMF_BS + 32)     // 54432 floats = 217,728 B

__global__ __launch_bounds__(256, 1)
void lstm_fused_kernel(const float* __restrict__ xg0,
                       const float* __restrict__ W_hh0,
                       const float* __restrict__ W_ih1,
                       const float* __restrict__ W_hh1,
                       const float* __restrict__ b_ih1,
                       const float* __restrict__ b_hh1,
                       uint2* hf0A, uint2* hf0B,
                       uint2* hf0loA, uint2* hf0loB,
                       uint2* hf1A, uint2* hf1B,
                       uint4* gWhh1,
                       float* __restrict__ hlast) {
    extern __shared__ float smem[];
    uint4* WfHi = (uint4*)(smem + SMF_WHI);
    uint4* WfLo = (uint4*)(smem + SMF_WLO);
    float* Ps  = smem + SMF_PS;
    float* Ds  = smem + SMF_DS;
    float* Xs  = smem + SMF_XS;
    float* bs1 = smem + SMF_BS;

    const int tid  = threadIdx.x;      // 256
    const int lane = tid & 31;
    const int w    = tid >> 5;         // warp 0..7
    const int g    = lane >> 2;
    const int tg   = lane & 3;
    const int bid  = blockIdx.x;
    const int j0   = bid * 8;
    const int bp   = lane;
    const int jl   = w;

    __shared__ unsigned s_e0;
    if (tid == 0) s_e0 = *(volatile unsigned*)&g_bar_epoch;
    __syncthreads();
    const unsigned e0 = s_e0;

    // ---- one-time: L0 W_hh0 fragments -> registers (proven layout) ----
    uint4 af0[8], af1[8];
#pragma unroll
    for (int kgl = 0; kgl < 8; kgl++) {
        int kg = w * 8 + kgl;
        int k0 = kg * 16 + 2 * tg;
        int kh = k0 + 8;
        int r;
        long rowA, rowB;
        r = g;       rowA = (long)((r >> 3) * Hh + j0 + (r & 7)) * Hh;
        r = g + 8;   rowB = (long)((r >> 3) * Hh + j0 + (r & 7)) * Hh;
        af0[kgl].x = pack_bf16x2(W_hh0[rowA + k0], W_hh0[rowA + k0 + 1]);
        af0[kgl].y = pack_bf16x2(W_hh0[rowB + k0], W_hh0[rowB + k0 + 1]);
        af0[kgl].z = pack_bf16x2(W_hh0[rowA + kh], W_hh0[rowA + kh + 1]);
        af0[kgl].w = pack_bf16x2(W_hh0[rowB + kh], W_hh0[rowB + kh + 1]);
        r = 16 + g;  rowA = (long)((r >> 3) * Hh + j0 + (r & 7)) * Hh;
        r = 24 + g;  rowB = (long)((r >> 3) * Hh + j0 + (r & 7)) * Hh;
        af1[kgl].x = pack_bf16x2(W_hh0[rowA + k0], W_hh0[rowA + k0 + 1]);
        af1[kgl].y = pack_bf16x2(W_hh0[rowB + k0], W_hh0[rowB + k0 + 1]);
        af1[kgl].z = pack_bf16x2(W_hh0[rowA + kh], W_hh0[rowA + kh + 1]);
        af1[kgl].w = pack_bf16x2(W_hh0[rowB + kh], W_hh0[rowB + kh + 1]);
    }

    // ---- one-time: W_ih1 split (hi/lo) fragments -> smem (K=1024) ----
    for (int i = tid; i < 4096; i += 256) {
        int l   = i & 31;
        int grp = i >> 5;             // kg*2 + mt
        int mt  = grp & 1;
        int kg  = grp >> 1;
        int gg = l >> 2, tt = l & 3;
        int kl = kg * 16 + 2 * tt;
        int kh = kl + 8;
        int rA = mt * 16 + gg;
        int rB = rA + 8;
        long rowA = (long)((rA >> 3) * Hh + j0 + (rA & 7)) * Hh;
        long rowB = (long)((rB >> 3) * Hh + j0 + (rB & 7)) * Hh;
        uint4 vh, vl;
        split_bf16x2(W_ih1[rowA + kl], W_ih1[rowA + kl + 1], vh.x, vl.x);
        split_bf16x2(W_ih1[rowB + kl], W_ih1[rowB + kl + 1], vh.y, vl.y);
        split_bf16x2(W_ih1[rowA + kh], W_ih1[rowA + kh + 1], vh.z, vl.z);
        split_bf16x2(W_ih1[rowB + kh], W_ih1[rowB + kh + 1], vh.w, vl.w);
        WfHi[i] = vh;
        WfLo[i] = vl;
    }

    // ---- one-time: W_hh1 bf16 fragments -> block-private GLOBAL ----
    uint4* myWhh = gWhh1 + (long)bid * 4096;
    for (int i = tid; i < 4096; i += 256) {
        int l   = i & 31;
        int grp = i >> 5;
        int mt  = grp & 1;
        int kg  = grp >> 1;
        int gg = l >> 2, tt = l & 3;
        int kl = kg * 16 + 2 * tt;
        int kh = kl + 8;
        int rA = mt * 16 + gg;
        int rB = rA + 8;
        long rowA = (long)((rA >> 3) * Hh + j0 + (rA & 7)) * Hh;
        long rowB = (long)((rB >> 3) * Hh + j0 + (rB & 7)) * Hh;
        uint4 v;
        v.x = pack_bf16x2(W_hh1[rowA + kl], W_hh1[rowA + kl + 1]);
        v.y = pack_bf16x2(W_hh1[rowB + kl], W_hh1[rowB + kl + 1]);
        v.z = pack_bf16x2(W_hh1[rowA + kh], W_hh1[rowA + kh + 1]);
        v.w = pack_bf16x2(W_hh1[rowB + kh], W_hh1[rowB + kh + 1]);
        myWhh[i] = v;
    }

    // ---- one-time: L1 bias sums ----
    if (tid < 32) {
        int gate = tid >> 3, jj = tid & 7;
        bs1[tid] = b_ih1[gate * Hh + j0 + jj] + b_hh1[gate * Hh + j0 + jj];
    }

    // producer frag-write geometry (proven)
    const int jj16 = ((bid & 1) << 3) + jl;
    const int tgp  = (jj16 & 7) >> 1;
    const int bsub = ((jj16 >= 8) ? 4 : 0) + (jj16 & 1) * 2;
    const int kgp  = bid >> 1;

    float cst0[2] = {0.f, 0.f};
    float cst1[2] = {0.f, 0.f};
    __syncthreads();   // also makes myWhh global writes visible block-wide

    // stage Xs for s=0
#pragma unroll
    for (int i = 0; i < 8; i++) {
        int idx = tid + i * 256;
        int jj = idx & 7;
        int gate = (idx >> 3) & 3;
        int b = idx >> 5;
        Xs[(gate * 8 + jj) * 64 + b] =
            xg0[((long)b * Tt + 0) * G4 + gate * Hh + j0 + jj];
    }

    for (int s = 0; s <= Tt; s++) {
        const uint2* hf0prev   = (s & 1) ? hf0A   : hf0B;
        uint2*       hf0out    = (s & 1) ? hf0B   : hf0A;
        const uint2* hf0loprev = (s & 1) ? hf0loA : hf0loB;
        uint2*       hf0loout  = (s & 1) ? hf0loB : hf0loA;
        const uint2* hf1prev   = (s & 1) ? hf1A   : hf1B;
        uint2*       hf1out    = (s & 1) ? hf1B   : hf1A;

        // ---- MERGED loop: B = h0_hi; feeds L0 (af) and L1-ih (WfHi+WfLo) ----
        float aL0[8][4], aL1[8][4];   // L0 accs (rows 0..15 / 16..31)
        float aM0[8][4], aM1[8][4];   // L1 accs
#pragma unroll
        for (int nt = 0; nt < 8; nt++)
#pragma unroll
            for (int r = 0; r < 4; r++) {
                aL0[nt][r] = 0.f; aL1[nt][r] = 0.f;
                aM0[nt][r] = 0.f; aM1[nt][r] = 0.f;
            }
        {
            const uint2* hb = hf0prev + (w * 64) * 32 + lane;
            uint2 Bq[4];
#pragma unroll
            for (int p = 0; p < 4; p++) Bq[p] = __ldcg(hb + p * 32);
#pragma unroll
            for (int kgl = 0; kgl < 8; kgl++) {
                uint4 wh0 = WfHi[((w * 8 + kgl) * 2 + 0) * 32 + lane];
                uint4 wh1 = WfHi[((w * 8 + kgl) * 2 + 1) * 32 + lane];
                uint4 wl0 = WfLo[((w * 8 + kgl) * 2 + 0) * 32 + lane];
                uint4 wl1 = WfLo[((w * 8 + kgl) * 2 + 1) * 32 + lane];
#pragma unroll
                for (int nt = 0; nt < 8; nt++) {
                    int i = kgl * 8 + nt;
                    uint2 B = Bq[i & 3];
                    if (i + 4 < 64) Bq[i & 3] = __ldcg(hb + (i + 4) * 32);
                    mma_bf16(aL0[nt], af0[kgl].x, af0[kgl].y, af0[kgl].z, af0[kgl].w, B.x, B.y);
                    mma_bf16(aL1[nt], af1[kgl].x, af1[kgl].y, af1[kgl].z, af1[kgl].w, B.x, B.y);
                    mma_bf16(aM0[nt], wh0.x, wh0.y, wh0.z, wh0.w, B.x, B.y);
                    mma_bf16(aM1[nt], wh1.x, wh1.y, wh1.z, wh1.w, B.x, B.y);
                    mma_bf16(aM0[nt], wl0.x, wl0.y, wl0.z, wl0.w, B.x, B.y);
                    mma_bf16(aM1[nt], wl1.x, wl1.y, wl1.z, wl1.w, B.x, B.y);
                }
            }
        }

        // ---- store L0 partials (frees aL regs) ----
        {
            float* myPs = Ps + w * 2176;
#pragma unroll
            for (int nt = 0; nt < 8; nt++) {
                int c0 = nt * 8 + tg * 2;
                *(float2*)&myPs[g * 68 + c0]        = make_float2(aL0[nt][0], aL0[nt][1]);
                *(float2*)&myPs[(g + 8) * 68 + c0]  = make_float2(aL0[nt][2], aL0[nt][3]);
                *(float2*)&myPs[(16 + g) * 68 + c0] = make_float2(aL1[nt][0], aL1[nt][1]);
                *(float2*)&myPs[(24 + g) * 68 + c0] = make_float2(aL1[nt][2], aL1[nt][3]);
            }
        }

        // ---- Pass 2: B = h0_lo; W = WfHi ----
        {
            const uint2* hb = hf0loprev + (w * 64) * 32 + lane;
            uint2 Bq[4];
#pragma unroll
            for (int p = 0; p < 4; p++) Bq[p] = __ldcg(hb + p * 32);
#pragma unroll
            for (int kgl = 0; kgl < 8; kgl++) {
                uint4 wh0 = WfHi[((w * 8 + kgl) * 2 + 0) * 32 + lane];
                uint4 wh1 = WfHi[((w * 8 + kgl) * 2 + 1) * 32 + lane];
#pragma unroll
                for (int nt = 0; nt < 8; nt++) {
                    int i = kgl * 8 + nt;
                    uint2 B = Bq[i & 3];
                    if (i + 4 < 64) Bq[i & 3] = __ldcg(hb + (i + 4) * 32);
                    mma_bf16(aM0[nt], wh0.x, wh0.y, wh0.z, wh0.w, B.x, B.y);
                    mma_bf16(aM1[nt], wh1.x, wh1.y, wh1.z, wh1.w, B.x, B.y);
                }
            }
        }
        // ---- Pass 3: B = h1_prev; W = gWhh1 (block-private, L2) ----
        {
            const uint2* hb = hf1prev + (w * 64) * 32 + lane;
            uint2 Bq[4];
#pragma unroll
            for (int p = 0; p < 4; p++) Bq[p] = __ldcg(hb + p * 32);
#pragma unroll
            for (int kgl = 0; kgl < 8; kgl++) {
                uint4 wh0 = __ldcg(myWhh + ((w * 8 + kgl) * 2 + 0) * 32 + lane);
                uint4 wh1 = __ldcg(myWhh + ((w * 8 + kgl) * 2 + 1) * 32 + lane);
#pragma unroll
                for (int nt = 0; nt < 8; nt++) {
                    int i = kgl * 8 + nt;
                    uint2 B = Bq[i & 3];
                    if (i + 4 < 64) Bq[i & 3] = __ldcg(hb + (i + 4) * 32);
                    mma_bf16(aM0[nt], wh0.x, wh0.y, wh0.z, wh0.w, B.x, B.y);
                    mma_bf16(aM1[nt], wh1.x, wh1.y, wh1.z, wh1.w, B.x, B.y);
                }
            }
        }
        __syncthreads();   // Ps(L0) complete

        // ---- reduce L0 partials -> Ds ----
        {
            int row  = tid >> 3;
            int col0 = (tid & 7) * 8;
            float4 s0 = make_float4(0.f, 0.f, 0.f, 0.f);
            float4 s1 = make_float4(0.f, 0.f, 0.f, 0.f);
#pragma unroll
            for (int ww = 0; ww < 8; ww++) {
                const float* p = Ps + ww * 2176 + row * 68 + col0;
                float4 a = *(const float4*)p;
                float4 b = *(const float4*)(p + 4);
                s0.x += a.x; s0.y += a.y; s0.z += a.z; s0.w += a.w;
                s1.x += b.x; s1.y += b.y; s1.z += b.z; s1.w += b.w;
            }
            *(float4*)&Ds[row * 68 + col0]     = s0;
            *(float4*)&Ds[row * 68 + col0 + 4] = s1;
        }
        __syncthreads();

        // ---- L0 pointwise + h0 frag writes; also store L1 partials to Ps ----
        if (s < Tt) {
#pragma unroll
            for (int bl = 0; bl < 2; bl++) {
                int b = bp * 2 + bl;
                float pi = Ds[jl * 68 + b]        + Xs[jl * 64 + b];
                float pf = Ds[(8 + jl) * 68 + b]  + Xs[(8 + jl) * 64 + b];
                float pg = Ds[(16 + jl) * 68 + b] + Xs[(16 + jl) * 64 + b];
                float po = Ds[(24 + jl) * 68 + b] + Xs[(24 + jl) * 64 + b];
                float gi = 1.f / (1.f + expf(-pi));
                float gf = 1.f / (1.f + expf(-pf));
                float gg2 = tanhf(pg);
                float go = 1.f / (1.f + expf(-po));
                float c = gf * cst0[bl] + gi * gg2;
                cst0[bl] = c;
                float h = go * tanhf(c);
                long fo = (kgp * 8 + (b >> 3)) * 32 + (b & 7) * 4 + tgp;
                __nv_bfloat16 hhi = __float2bfloat16_rn(h);
                float hlo = h - __bfloat162float(hhi);
                *(__nv_bfloat16*)((char*)(hf0out + fo) + bsub)   = hhi;
                *(__nv_bfloat16*)((char*)(hf0loout + fo) + bsub) = __float2bfloat16_rn(hlo);
            }
        }
        {   // L1 partials (Ps safe to overwrite: all threads passed the reduce)
            float* myPs = Ps + w * 2176;
#pragma unroll
            for (int nt = 0; nt < 8; nt++) {
                int c0 = nt * 8 + tg * 2;
                *(float2*)&myPs[g * 68 + c0]        = make_float2(aM0[nt][0], aM0[nt][1]);
                *(float2*)&myPs[(g + 8) * 68 + c0]  = make_float2(aM0[nt][2], aM0[nt][3]);
                *(float2*)&myPs[(16 + g) * 68 + c0] = make_float2(aM1[nt][0], aM1[nt][1]);
                *(float2*)&myPs[(24 + g) * 68 + c0] = make_float2(aM1[nt][2], aM1[nt][3]);
            }
        }
        __syncthreads();

        // ---- reduce L1 partials -> Ds ----
        {
            int row  = tid >> 3;
            int col0 = (tid & 7) * 8;
            float4 s0 = make_float4(0.f, 0.f, 0.f, 0.f);
            float4 s1 = make_float4(0.f, 0.f, 0.f, 0.f);
#pragma unroll
            for (int ww = 0; ww < 8; ww++) {
                const float* p = Ps + ww * 2176 + row * 68 + col0;
                float4 a = *(const float4*)p;
                float4 b = *(const float4*)(p + 4);
                s0.x += a.x; s0.y += a.y; s0.z += a.z; s0.w += a.w;
                s1.x += b.x; s1.y += b.y; s1.z += b.z; s1.w += b.w;
            }
            *(float4*)&Ds[row * 68 + col0]     = s0;
            *(float4*)&Ds[row * 68 + col0 + 4] = s1;
        }
        __syncthreads();

        // ---- L1 pointwise + h1 frag writes ----
        if (s >= 1) {
#pragma unroll
            for (int bl = 0; bl < 2; bl++) {
                int b = bp * 2 + bl;
                float pi = Ds[jl * 68 + b]        + bs1[jl];
                float pf = Ds[(8 + jl) * 68 + b]  + bs1[8 + jl];
                float pg = Ds[(16 + jl) * 68 + b] + bs1[16 + jl];
                float po = Ds[(24 + jl) * 68 + b] + bs1[24 + jl];
                float gi = 1.f / (1.f + expf(-pi));
                float gf = 1.f / (1.f + expf(-pf));
                float gg2 = tanhf(pg);
                float go = 1.f / (1.f + expf(-po));
                float c = gf * cst1[bl] + gi * gg2;
                cst1[bl] = c;
                float h = go * tanhf(c);
                char* fp = (char*)(hf1out + ((kgp * 8 + (b >> 3)) * 32 + (b & 7) * 4 + tgp)) + bsub;
                *(__nv_bfloat16*)fp = __float2bfloat16_rn(h);
                if (s == Tt) hlast[(long)b * Hh + j0 + jl] = h;
            }
        }

        __threadfence();
        __syncthreads();

        // ---- arrive ----
        if (tid == 0) {
            unsigned arrived = atomicAdd(&g_bar_count, 1u);
            if (arrived == NBLK - 1) {
                *(volatile unsigned*)&g_bar_count = 0u;
                __threadfence();
                *(volatile unsigned*)&g_bar_epoch = e0 + (unsigned)s + 1u;
            }
        }

        // ---- overlapped tail: stage next Xs ----
        if (s + 1 < Tt) {
#pragma unroll
            for (int i = 0; i < 8; i++) {
                int idx = tid + i * 256;
                int jj = idx & 7;
                int gate = (idx >> 3) & 3;
                int b = idx >> 5;
                Xs[(gate * 8 + jj) * 64 + b] =
                    xg0[((long)b * Tt + (s + 1)) * G4 + gate * Hh + j0 + jj];
            }
        }

        // ---- wait ----
        if (tid == 0) {
            while (*(volatile unsigned*)&g_bar_epoch < e0 + (unsigned)s + 1u) { }
        }
        __syncthreads();
    }
}

// ---------------------------------------------------------------------------
// kernel_launch: 4 graph nodes
// ---------------------------------------------------------------------------
extern "C" void kernel_launch(void* const* d_in, const int* in_sizes, int n_in,
                              void* d_out, int out_size) {
    const float* x     = (const float*)d_in[0];
    const float* W_ih0 = (const float*)d_in[1];
    const float* W_hh0 = (const float*)d_in[2];
    const float* b_ih0 = (const float*)d_in[3];
    const float* b_hh0 = (const float*)d_in[4];
    const float* W_ih1 = (const float*)d_in[5];
    const float* W_hh1 = (const float*)d_in[6];
    const float* b_ih1 = (const float*)d_in[7];
    const float* b_hh1 = (const float*)d_in[8];
    const float* fc_w  = (const float*)d_in[9];
    const float* fc_b  = (const float*)d_in[10];
    float* out = (float*)d_out;

    float *xg, *hlast;
    uint2 *hf0A, *hf0B, *hf0loA, *hf0loB, *hf1A, *hf1B;
    uint4 *gWhh1;
    cudaGetSymbolAddress((void**)&xg, g_xg);
    cudaGetSymbolAddress((void**)&hf0A, g_hf0A);
    cudaGetSymbolAddress((void**)&hf0B, g_hf0B);
    cudaGetSymbolAddress((void**)&hf0loA, g_hf0loA);
    cudaGetSymbolAddress((void**)&hf0loB, g_hf0loB);
    cudaGetSymbolAddress((void**)&hf1A, g_hf1A);
    cudaGetSymbolAddress((void**)&hf1B, g_hf1B);
    cudaGetSymbolAddress((void**)&gWhh1, g_Wf1hh);
    cudaGetSymbolAddress((void**)&hlast, g_hlast);

    const int fragN = 64 * 8 * 32 * 2;                  // uint32 per frag buffer
    const int SMEM_FUSED = SMF_TOT * sizeof(float);     // 217,728 B
    const int SMEM_GEMM  = 4 * 4608 * sizeof(float);    // 73,728 B

    static int smem_set = 0;
    if (!smem_set) {
        cudaFuncSetAttribute(lstm_fused_kernel,
                             cudaFuncAttributeMaxDynamicSharedMemorySize,
                             SMEM_FUSED);
        cudaFuncSetAttribute(tf32_gemm_async_kernel,
                             cudaFuncAttributeMaxDynamicSharedMemorySize,
                             SMEM_GEMM);
        smem_set = 1;
    }

    // zero the six h frag ring buffers
    zero6_kernel<<<(fragN + 255) / 256, 256>>>((float*)hf0A, (float*)hf0B,
                                               (float*)hf0loA, (float*)hf0loB,
                                               (float*)hf1A, (float*)hf1B, fragN);

    // xg0 = x @ W_ih0^T + b_ih0 + b_hh0   (M=32768, N=4096, K=512)
    {
        dim3 grid(G4 / 128, (Bb * Tt) / 128);
        tf32_gemm_async_kernel<<<grid, 256, SMEM_GEMM>>>(x, W_ih0, b_ih0, b_hh0, xg,
                                                         Bb * Tt, G4, IN_DIM);
    }

    // fused 2-layer recurrence (513 wavefront iterations)
    lstm_fused_kernel<<<NBLK, 256, SMEM_FUSED>>>(
        xg, W_hh0, W_ih1, W_hh1, b_ih1, b_hh1,
        hf0A, hf0B, hf0loA, hf0loB, hf1A, hf1B, gWhh1, hlast);

    // FC: out[64,1000] = hlast @ fc_w^T + fc_b
    {
        dim3 grid((NCLS + 63) / 64, (Bb + 127) / 128);
        sgemm_bias_kernel<<<grid, 256>>>(hlast, fc_w, fc_b, nullptr, out,
                                         Bb, NCLS, Hh);
    }
}